// round 1
// baseline (speedup 1.0000x reference)
#include <cuda_runtime.h>
#include <math.h>

#define HIDDEN 1024
#define HEADS  16
#define KD     64
#define NB     4
#define SEQ    2048
#define MTOT   (NB * SEQ)          /* 8192 rows */
#define SCALE  0.125f              /* 1/sqrt(64) */

/* ---------------- scratch (device globals: no allocs allowed) ------------- */
__device__ float g_q[MTOT * HIDDEN];
__device__ float g_k[MTOT * HIDDEN];
__device__ float g_v[MTOT * HIDDEN];
__device__ float g_ctx[MTOT * HIDDEN];

/* ---------------- generic fp32 GEMM:  Y = X @ W^T + bias ------------------ *
 * X: [M,K] row-major, W: [N,K] row-major (so dot(X_row, W_row)), Y: [M,N].
 * 128x128 block tile, BK=8, 256 threads, 8x8 per-thread accumulators.
 */
__global__ __launch_bounds__(256, 2)
void gemm_bias_kernel(const float* __restrict__ X, const float* __restrict__ W,
                      const float* __restrict__ bias, float* __restrict__ Y,
                      int M, int N, int K)
{
    __shared__ float As[8][128];   /* [k][m] */
    __shared__ float Bs[8][128];   /* [k][n] */

    const int tid = threadIdx.x;
    const int bm  = blockIdx.y * 128;
    const int bn  = blockIdx.x * 128;

    const int lr = tid >> 1;            /* 0..127 : tile row loaded */
    const int lc = (tid & 1) * 4;       /* 0 or 4 : k offset        */
    const int tx = tid & 15;            /* 0..15  : 8-col group     */
    const int ty = tid >> 4;            /* 0..15  : 8-row group     */

    const float* Ap = X + (size_t)(bm + lr) * K + lc;
    const float* Bp = W + (size_t)(bn + lr) * K + lc;

    float acc[8][8];
#pragma unroll
    for (int i = 0; i < 8; i++)
#pragma unroll
        for (int j = 0; j < 8; j++) acc[i][j] = 0.f;

    for (int k0 = 0; k0 < K; k0 += 8) {
        float4 a4 = *(const float4*)(Ap + k0);
        float4 b4 = *(const float4*)(Bp + k0);
        As[lc + 0][lr] = a4.x; As[lc + 1][lr] = a4.y;
        As[lc + 2][lr] = a4.z; As[lc + 3][lr] = a4.w;
        Bs[lc + 0][lr] = b4.x; Bs[lc + 1][lr] = b4.y;
        Bs[lc + 2][lr] = b4.z; Bs[lc + 3][lr] = b4.w;
        __syncthreads();

#pragma unroll
        for (int kk = 0; kk < 8; kk++) {
            float4 ra0 = *(const float4*)&As[kk][ty * 8];
            float4 ra1 = *(const float4*)&As[kk][ty * 8 + 4];
            float4 rb0 = *(const float4*)&Bs[kk][tx * 8];
            float4 rb1 = *(const float4*)&Bs[kk][tx * 8 + 4];
            float ra[8] = {ra0.x, ra0.y, ra0.z, ra0.w, ra1.x, ra1.y, ra1.z, ra1.w};
            float rb[8] = {rb0.x, rb0.y, rb0.z, rb0.w, rb1.x, rb1.y, rb1.z, rb1.w};
#pragma unroll
            for (int i = 0; i < 8; i++)
#pragma unroll
                for (int j = 0; j < 8; j++)
                    acc[i][j] += ra[i] * rb[j];
        }
        __syncthreads();
    }

#pragma unroll
    for (int i = 0; i < 8; i++) {
        const int row = bm + ty * 8 + i;
        float* yp = Y + (size_t)row * N + bn + tx * 8;
        const float* bp = bias + bn + tx * 8;
#pragma unroll
        for (int j = 0; j < 8; j++) yp[j] = acc[i][j] + bp[j];
    }
}

/* ---------------- RoPE (in place on [MTOT, HEADS, 64], first 32 dims) ----- */
__global__ void rope_kernel(float* __restrict__ x)
{
    int idx = blockIdx.x * blockDim.x + threadIdx.x;  /* MTOT*HEADS*16 */
    if (idx >= MTOT * HEADS * 16) return;
    const int t   = idx & 15;
    const int h   = (idx >> 4) & (HEADS - 1);
    const int row = idx >> 8;
    const int s   = row & (SEQ - 1);

    const float theta = powf(10000.f, -(float)t * (1.f / 16.f));
    const float ang   = (float)s * theta;
    float si, c;
    sincosf(ang, &si, &c);

    float* p = x + (size_t)row * HIDDEN + h * KD;
    const float x0 = p[t];
    const float x1 = p[t + 16];
    p[t]      = x0 * c - x1 * si;
    p[t + 16] = x1 * c + x0 * si;
}

/* ---------------- fused flash attention (fp32, online softmax) ------------ *
 * Grid: (SEQ/64, NB*HEADS). Block: 128 threads.
 * Per block: 64 query rows x D=64, loop over 64-wide K/V tiles.
 * Thread (tx=tid&7, ty=tid>>3) owns 4 rows x 8 cols of S / O.
 * smem: Qt[d][i], KtPt[.][.] (Kt during QK, Pt[j][i] during PV), Vs[j][d].
 */
__global__ __launch_bounds__(128)
void attn_kernel(const float* __restrict__ Q, const float* __restrict__ K,
                 const float* __restrict__ V, float* __restrict__ O)
{
    __shared__ float Qt[64][64];    /* [d][i] */
    __shared__ float KtPt[64][64];  /* Kt: [d][j]  then  Pt: [j][i] */
    __shared__ float Vs[64][64];    /* [j][d] */

    const int tid = threadIdx.x;
    const int tx  = tid & 7;        /* 8-col group  (j or d)  */
    const int ty  = tid >> 3;       /* 4-row group  (i)       */
    const int bh  = blockIdx.y;
    const int b   = bh >> 4;
    const int h   = bh & (HEADS - 1);
    const int i0  = blockIdx.x * 64;

    const size_t base = ((size_t)b * SEQ) * HIDDEN + (size_t)h * KD;

    /* load Q tile transposed: Qt[d][i] */
    {
        const int r  = tid >> 1;
        const int c4 = (tid & 1) * 4;
#pragma unroll
        for (int p = 0; p < 8; p++) {
            const int d = p * 8 + c4;
            float4 v = *(const float4*)&Q[base + (size_t)(i0 + r) * HIDDEN + d];
            Qt[d + 0][r] = v.x; Qt[d + 1][r] = v.y;
            Qt[d + 2][r] = v.z; Qt[d + 3][r] = v.w;
        }
    }

    float m[4], l[4], o[4][8];
#pragma unroll
    for (int r = 0; r < 4; r++) {
        m[r] = -1e30f; l[r] = 0.f;
#pragma unroll
        for (int c = 0; c < 8; c++) o[r][c] = 0.f;
    }

    for (int j0 = 0; j0 < SEQ; j0 += 64) {
        __syncthreads();  /* prev-iter Pt/Vs reads (and initial Qt writes) done */

        /* load K transposed -> KtPt[d][j], V -> Vs[j][d] */
        {
            const int r  = tid >> 1;
            const int c4 = (tid & 1) * 4;
#pragma unroll
            for (int p = 0; p < 8; p++) {
                const int d = p * 8 + c4;
                float4 kv = *(const float4*)&K[base + (size_t)(j0 + r) * HIDDEN + d];
                KtPt[d + 0][r] = kv.x; KtPt[d + 1][r] = kv.y;
                KtPt[d + 2][r] = kv.z; KtPt[d + 3][r] = kv.w;
                float4 vv = *(const float4*)&V[base + (size_t)(j0 + r) * HIDDEN + d];
                *(float4*)&Vs[r][d] = vv;
            }
        }
        __syncthreads();

        /* S = Q K^T for this tile: s[r][c], i = ty*4+r, j = tx*8+c */
        float s[4][8];
#pragma unroll
        for (int r = 0; r < 4; r++)
#pragma unroll
            for (int c = 0; c < 8; c++) s[r][c] = 0.f;

#pragma unroll 4
        for (int d = 0; d < 64; d++) {
            float4 qa  = *(const float4*)&Qt[d][ty * 4];
            float4 kb0 = *(const float4*)&KtPt[d][tx * 8];
            float4 kb1 = *(const float4*)&KtPt[d][tx * 8 + 4];
            float ra[4] = {qa.x, qa.y, qa.z, qa.w};
            float rb[8] = {kb0.x, kb0.y, kb0.z, kb0.w, kb1.x, kb1.y, kb1.z, kb1.w};
#pragma unroll
            for (int r = 0; r < 4; r++)
#pragma unroll
                for (int c = 0; c < 8; c++)
                    s[r][c] += ra[r] * rb[c];
        }
        __syncthreads();  /* Kt reads done before Pt overwrites the buffer */

        /* online softmax; write P transposed into KtPt as Pt[j][i] */
#pragma unroll
        for (int r = 0; r < 4; r++) {
            float mt = -1e30f;
#pragma unroll
            for (int c = 0; c < 8; c++) {
                s[r][c] *= SCALE;
                mt = fmaxf(mt, s[r][c]);
            }
#pragma unroll
            for (int off = 1; off < 8; off <<= 1)
                mt = fmaxf(mt, __shfl_xor_sync(0xffffffffu, mt, off));

            const float mn   = fmaxf(m[r], mt);
            const float corr = __expf(m[r] - mn);
            float rs = 0.f;
#pragma unroll
            for (int c = 0; c < 8; c++) {
                const float pv = __expf(s[r][c] - mn);
                rs += pv;
                KtPt[tx * 8 + c][ty * 4 + r] = pv;   /* Pt[j][i] */
            }
#pragma unroll
            for (int off = 1; off < 8; off <<= 1)
                rs += __shfl_xor_sync(0xffffffffu, rs, off);

            l[r] = l[r] * corr + rs;
            m[r] = mn;
#pragma unroll
            for (int c = 0; c < 8; c++) o[r][c] *= corr;
        }
        __syncthreads();

        /* O += P V : o[r][c], i = ty*4+r, dcol = tx*8+c */
#pragma unroll 4
        for (int j = 0; j < 64; j++) {
            float4 pa  = *(const float4*)&KtPt[j][ty * 4];   /* Pt[j][i..] */
            float4 vb0 = *(const float4*)&Vs[j][tx * 8];
            float4 vb1 = *(const float4*)&Vs[j][tx * 8 + 4];
            float ra[4] = {pa.x, pa.y, pa.z, pa.w};
            float rb[8] = {vb0.x, vb0.y, vb0.z, vb0.w, vb1.x, vb1.y, vb1.z, vb1.w};
#pragma unroll
            for (int r = 0; r < 4; r++)
#pragma unroll
                for (int c = 0; c < 8; c++)
                    o[r][c] += ra[r] * rb[c];
        }
    }

    /* normalize and write context [b, i, h*64+d] */
#pragma unroll
    for (int r = 0; r < 4; r++) {
        const float inv = 1.f / l[r];
        const int row = i0 + ty * 4 + r;
        float* op = O + base + (size_t)row * HIDDEN + tx * 8;
#pragma unroll
        for (int c = 0; c < 8; c++) op[c] = o[r][c] * inv;
    }
}

/* ---------------- launch ------------------------------------------------- */
extern "C" void kernel_launch(void* const* d_in, const int* in_sizes, int n_in,
                              void* d_out, int out_size)
{
    (void)in_sizes; (void)n_in; (void)out_size;

    const float* query = (const float*)d_in[0];
    const float* value = (const float*)d_in[1];
    const float* Wq    = (const float*)d_in[2];
    const float* bq    = (const float*)d_in[3];
    const float* Wk    = (const float*)d_in[4];
    const float* bk    = (const float*)d_in[5];
    const float* Wv    = (const float*)d_in[6];
    const float* bv    = (const float*)d_in[7];
    const float* Wo    = (const float*)d_in[8];
    const float* bo    = (const float*)d_in[9];
    float* out = (float*)d_out;

    float *q, *k, *v, *ctx;
    cudaGetSymbolAddress((void**)&q,   g_q);
    cudaGetSymbolAddress((void**)&k,   g_k);
    cudaGetSymbolAddress((void**)&v,   g_v);
    cudaGetSymbolAddress((void**)&ctx, g_ctx);

    dim3 gg(HIDDEN / 128, MTOT / 128);   /* (8, 64) */

    gemm_bias_kernel<<<gg, 256>>>(query, Wq, bq, q, MTOT, HIDDEN, HIDDEN);
    gemm_bias_kernel<<<gg, 256>>>(value, Wk, bk, k, MTOT, HIDDEN, HIDDEN);
    gemm_bias_kernel<<<gg, 256>>>(value, Wv, bv, v, MTOT, HIDDEN, HIDDEN);

    const int rope_threads = MTOT * HEADS * 16;       /* 2M */
    rope_kernel<<<rope_threads / 256, 256>>>(q);
    rope_kernel<<<rope_threads / 256, 256>>>(k);

    attn_kernel<<<dim3(SEQ / 64, NB * HEADS), 128>>>(q, k, v, ctx);

    gemm_bias_kernel<<<gg, 256>>>(ctx, Wo, bo, out, MTOT, HIDDEN, HIDDEN);
}

// round 4
// speedup vs baseline: 1.3076x; 1.3076x over previous
#include <cuda_runtime.h>
#include <cuda_bf16.h>
#include <math.h>
#include <stdint.h>

#define HIDDEN 1024
#define HEADS  16
#define KD     64
#define NB     4
#define SEQ    2048
#define MTOT   (NB * SEQ)          /* 8192 rows */
#define SCALE  0.125f              /* 1/sqrt(64) */

/* ---------------- scratch (device globals: no allocs allowed) ------------- */
__device__ float g_q[MTOT * HIDDEN];
__device__ float g_k[MTOT * HIDDEN];
__device__ float g_v[MTOT * HIDDEN];
__device__ float g_ctx[MTOT * HIDDEN];

__device__ __nv_bfloat16 g_qryhi[MTOT * HIDDEN];
__device__ __nv_bfloat16 g_qrylo[MTOT * HIDDEN];
__device__ __nv_bfloat16 g_valhi[MTOT * HIDDEN];
__device__ __nv_bfloat16 g_vallo[MTOT * HIDDEN];
__device__ __nv_bfloat16 g_ctxhi[MTOT * HIDDEN];
__device__ __nv_bfloat16 g_ctxlo[MTOT * HIDDEN];
__device__ __nv_bfloat16 g_whi[4 * HIDDEN * HIDDEN];
__device__ __nv_bfloat16 g_wlo[4 * HIDDEN * HIDDEN];

/* ======================= PTX helpers (sm_80-portable) ===================== */
__device__ __forceinline__ uint32_t smem_u32(const void* p) {
    uint32_t a;
    asm("{ .reg .u64 t; cvta.to.shared.u64 t, %1; cvt.u32.u64 %0, t; }"
        : "=r"(a) : "l"(p));
    return a;
}
__device__ __forceinline__ void cp16(uint32_t dst, const void* src) {
    asm volatile("cp.async.cg.shared.global [%0], [%1], 16;"
                 :: "r"(dst), "l"(src));
}
__device__ __forceinline__ void cp_commit() {
    asm volatile("cp.async.commit_group;" ::: "memory");
}
__device__ __forceinline__ void cp_wait0() {
    asm volatile("cp.async.wait_group 0;" ::: "memory");
}
__device__ __forceinline__ void cp_wait1() {
    asm volatile("cp.async.wait_group 1;" ::: "memory");
}
__device__ __forceinline__ void ldmx4(uint32_t* r, uint32_t a) {
    asm volatile("ldmatrix.sync.aligned.m8n8.x4.shared.b16 {%0,%1,%2,%3}, [%4];"
                 : "=r"(r[0]), "=r"(r[1]), "=r"(r[2]), "=r"(r[3]) : "r"(a));
}
__device__ __forceinline__ void mma_bf16(float* c, const uint32_t* a,
                                         uint32_t b0, uint32_t b1) {
    asm volatile(
        "mma.sync.aligned.m16n8k16.row.col.f32.bf16.bf16.f32 "
        "{%0,%1,%2,%3}, {%4,%5,%6,%7}, {%8,%9}, {%0,%1,%2,%3};"
        : "+f"(c[0]), "+f"(c[1]), "+f"(c[2]), "+f"(c[3])
        : "r"(a[0]), "r"(a[1]), "r"(a[2]), "r"(a[3]), "r"(b0), "r"(b1));
}

/* ======================= split fp32 -> (hi,lo) bf16 ======================= */
__global__ void split4_kernel(const float4* __restrict__ x,
                              uint2* __restrict__ hi, uint2* __restrict__ lo, int n4)
{
    int i = blockIdx.x * blockDim.x + threadIdx.x;
    if (i >= n4) return;
    float4 v = x[i];
    __nv_bfloat16 h0 = __float2bfloat16(v.x);
    __nv_bfloat16 h1 = __float2bfloat16(v.y);
    __nv_bfloat16 h2 = __float2bfloat16(v.z);
    __nv_bfloat16 h3 = __float2bfloat16(v.w);
    __nv_bfloat16 l0 = __float2bfloat16(v.x - __bfloat162float(h0));
    __nv_bfloat16 l1 = __float2bfloat16(v.y - __bfloat162float(h1));
    __nv_bfloat16 l2 = __float2bfloat16(v.z - __bfloat162float(h2));
    __nv_bfloat16 l3 = __float2bfloat16(v.w - __bfloat162float(h3));
    uint2 H, L;
    H.x = (uint32_t)__bfloat16_as_ushort(h0) | ((uint32_t)__bfloat16_as_ushort(h1) << 16);
    H.y = (uint32_t)__bfloat16_as_ushort(h2) | ((uint32_t)__bfloat16_as_ushort(h3) << 16);
    L.x = (uint32_t)__bfloat16_as_ushort(l0) | ((uint32_t)__bfloat16_as_ushort(l1) << 16);
    L.y = (uint32_t)__bfloat16_as_ushort(l2) | ((uint32_t)__bfloat16_as_ushort(l3) << 16);
    hi[i] = H;
    lo[i] = L;
}

/* ======================= mma.sync GEMM (bf16x3) =========================== *
 * Y[M,N] = (Ahi+Alo)[M,K] @ (Bhi+Blo)[N,K]^T + bias, fp32 out.
 * CTA 128x128, 256 thr = 8 warps (2m x 4n), warp tile 64x32.
 * K-chunk 16, double-buffered cp.async, 48KB static smem.
 * 3 MMAs per frag-pair: hi*hi + hi*lo + lo*hi.
 */
#define ST    24                 /* padded row stride in bf16 (16 data + 8 pad) */
#define TILEB (128 * ST * 2)     /* 6144 B per tile */

__global__ __launch_bounds__(256)
void gemm_mma_kernel(const __nv_bfloat16* __restrict__ Ahi,
                     const __nv_bfloat16* __restrict__ Alo,
                     const __nv_bfloat16* __restrict__ Bhi,
                     const __nv_bfloat16* __restrict__ Blo,
                     const float* __restrict__ bias,
                     float* __restrict__ Y)
{
    __shared__ __align__(16) char sm[2 * 4 * TILEB];   /* 49152 B */

    const int tid  = threadIdx.x;
    const int lane = tid & 31;
    const int warp = tid >> 5;
    const int wm   = warp >> 2;          /* 0..1 */
    const int wn   = warp & 3;           /* 0..3 */
    const int bm   = blockIdx.y * 128;
    const int bn   = blockIdx.x * 128;

    const uint32_t sb = smem_u32(sm);

    const __nv_bfloat16* srcs[4] = {
        Ahi + (size_t)bm * HIDDEN, Alo + (size_t)bm * HIDDEN,
        Bhi + (size_t)bn * HIDDEN, Blo + (size_t)bn * HIDDEN
    };

    /* loader: per stage, per tile: 256 chunks of 16B; 1 chunk per thread */
    const int lrow  = tid >> 1;          /* 0..127 */
    const int lpart = tid & 1;           /* 0..1   */

#define LOAD_STAGE(s, k0)                                                     \
    do {                                                                      \
        _Pragma("unroll")                                                     \
        for (int t = 0; t < 4; t++) {                                         \
            uint32_t dst = sb + ((s) * 4 + t) * TILEB + lrow * 48 + lpart * 16; \
            const char* src = (const char*)(srcs[t] + (size_t)lrow * HIDDEN + (k0)) \
                              + lpart * 16;                                   \
            cp16(dst, src);                                                   \
        }                                                                     \
        cp_commit();                                                          \
    } while (0)

    float acc[4][4][4];
#pragma unroll
    for (int mi = 0; mi < 4; mi++)
#pragma unroll
        for (int ni = 0; ni < 4; ni++)
#pragma unroll
            for (int e = 0; e < 4; e++) acc[mi][ni][e] = 0.f;

    LOAD_STAGE(0, 0);

    /* fragment addressing (within a tile) */
    const int arow  = wm * 64 + (lane & 15);
    const int acolb = (lane >> 4) << 4;                    /* 0 or 16 bytes */
    const int brow  = wn * 32 + (lane & 7) + ((lane >> 4) << 3);
    const int bcolb = ((lane >> 3) & 1) << 4;

    for (int ck = 0; ck < HIDDEN / 16; ck++) {
        if (ck < HIDDEN / 16 - 1) {
            LOAD_STAGE((ck + 1) & 1, (ck + 1) * 16);
            cp_wait1();
        } else {
            cp_wait0();
        }
        __syncthreads();

        const uint32_t base = sb + (ck & 1) * 4 * TILEB;
        const uint32_t aHiB = base;
        const uint32_t aLoB = base + TILEB;
        const uint32_t bHiB = base + 2 * TILEB;
        const uint32_t bLoB = base + 3 * TILEB;

        uint32_t ah[4][4], al[4][4], bh[2][4], bl[2][4];
#pragma unroll
        for (int mi = 0; mi < 4; mi++) {
            ldmx4(ah[mi], aHiB + (arow + mi * 16) * 48 + acolb);
            ldmx4(al[mi], aLoB + (arow + mi * 16) * 48 + acolb);
        }
#pragma unroll
        for (int nb = 0; nb < 2; nb++) {
            ldmx4(bh[nb], bHiB + (brow + nb * 16) * 48 + bcolb);
            ldmx4(bl[nb], bLoB + (brow + nb * 16) * 48 + bcolb);
        }

#pragma unroll
        for (int mi = 0; mi < 4; mi++)
#pragma unroll
            for (int ni = 0; ni < 4; ni++) {
                const int nb = ni >> 1, o = (ni & 1) * 2;
                mma_bf16(acc[mi][ni], ah[mi], bh[nb][o], bh[nb][o + 1]);
                mma_bf16(acc[mi][ni], ah[mi], bl[nb][o], bl[nb][o + 1]);
                mma_bf16(acc[mi][ni], al[mi], bh[nb][o], bh[nb][o + 1]);
            }

        __syncthreads();
    }

    /* epilogue: c0,c1 -> (row, col..col+1); c2,c3 -> (row+8, ...) */
#pragma unroll
    for (int ni = 0; ni < 4; ni++) {
        const int col = bn + wn * 32 + ni * 8 + (lane & 3) * 2;
        const float b0 = bias[col], b1 = bias[col + 1];
#pragma unroll
        for (int mi = 0; mi < 4; mi++) {
            const int row = bm + wm * 64 + mi * 16 + (lane >> 2);
            float2 v0 = make_float2(acc[mi][ni][0] + b0, acc[mi][ni][1] + b1);
            float2 v1 = make_float2(acc[mi][ni][2] + b0, acc[mi][ni][3] + b1);
            *(float2*)&Y[(size_t)row * HIDDEN + col]       = v0;
            *(float2*)&Y[(size_t)(row + 8) * HIDDEN + col] = v1;
        }
    }
#undef LOAD_STAGE
}

/* ---------------- RoPE (in place on [MTOT, HEADS, 64], first 32 dims) ----- */
__global__ void rope_kernel(float* __restrict__ x)
{
    int idx = blockIdx.x * blockDim.x + threadIdx.x;  /* MTOT*HEADS*16 */
    if (idx >= MTOT * HEADS * 16) return;
    const int t   = idx & 15;
    const int h   = (idx >> 4) & (HEADS - 1);
    const int row = idx >> 8;
    const int s   = row & (SEQ - 1);

    const float theta = powf(10000.f, -(float)t * (1.f / 16.f));
    const float ang   = (float)s * theta;
    float si, c;
    sincosf(ang, &si, &c);

    float* p = x + (size_t)row * HIDDEN + h * KD;
    const float x0 = p[t];
    const float x1 = p[t + 16];
    p[t]      = x0 * c - x1 * si;
    p[t + 16] = x1 * c + x0 * si;
}

/* ---------------- fused flash attention (fp32, online softmax) ------------ */
__global__ __launch_bounds__(128)
void attn_kernel(const float* __restrict__ Q, const float* __restrict__ K,
                 const float* __restrict__ V, float* __restrict__ O)
{
    __shared__ float Qt[64][64];    /* [d][i] */
    __shared__ float KtPt[64][64];  /* Kt: [d][j]  then  Pt: [j][i] */
    __shared__ float Vs[64][64];    /* [j][d] */

    const int tid = threadIdx.x;
    const int tx  = tid & 7;
    const int ty  = tid >> 3;
    const int bh  = blockIdx.y;
    const int b   = bh >> 4;
    const int h   = bh & (HEADS - 1);
    const int i0  = blockIdx.x * 64;

    const size_t base = ((size_t)b * SEQ) * HIDDEN + (size_t)h * KD;

    {
        const int r  = tid >> 1;
        const int c4 = (tid & 1) * 4;
#pragma unroll
        for (int p = 0; p < 8; p++) {
            const int d = p * 8 + c4;
            float4 v = *(const float4*)&Q[base + (size_t)(i0 + r) * HIDDEN + d];
            Qt[d + 0][r] = v.x; Qt[d + 1][r] = v.y;
            Qt[d + 2][r] = v.z; Qt[d + 3][r] = v.w;
        }
    }

    float m[4], l[4], o[4][8];
#pragma unroll
    for (int r = 0; r < 4; r++) {
        m[r] = -1e30f; l[r] = 0.f;
#pragma unroll
        for (int c = 0; c < 8; c++) o[r][c] = 0.f;
    }

    for (int j0 = 0; j0 < SEQ; j0 += 64) {
        __syncthreads();

        {
            const int r  = tid >> 1;
            const int c4 = (tid & 1) * 4;
#pragma unroll
            for (int p = 0; p < 8; p++) {
                const int d = p * 8 + c4;
                float4 kv = *(const float4*)&K[base + (size_t)(j0 + r) * HIDDEN + d];
                KtPt[d + 0][r] = kv.x; KtPt[d + 1][r] = kv.y;
                KtPt[d + 2][r] = kv.z; KtPt[d + 3][r] = kv.w;
                float4 vv = *(const float4*)&V[base + (size_t)(j0 + r) * HIDDEN + d];
                *(float4*)&Vs[r][d] = vv;
            }
        }
        __syncthreads();

        float s[4][8];
#pragma unroll
        for (int r = 0; r < 4; r++)
#pragma unroll
            for (int c = 0; c < 8; c++) s[r][c] = 0.f;

#pragma unroll 4
        for (int d = 0; d < 64; d++) {
            float4 qa  = *(const float4*)&Qt[d][ty * 4];
            float4 kb0 = *(const float4*)&KtPt[d][tx * 8];
            float4 kb1 = *(const float4*)&KtPt[d][tx * 8 + 4];
            float ra[4] = {qa.x, qa.y, qa.z, qa.w};
            float rbv[8] = {kb0.x, kb0.y, kb0.z, kb0.w, kb1.x, kb1.y, kb1.z, kb1.w};
#pragma unroll
            for (int r = 0; r < 4; r++)
#pragma unroll
                for (int c = 0; c < 8; c++)
                    s[r][c] += ra[r] * rbv[c];
        }
        __syncthreads();

#pragma unroll
        for (int r = 0; r < 4; r++) {
            float mt = -1e30f;
#pragma unroll
            for (int c = 0; c < 8; c++) {
                s[r][c] *= SCALE;
                mt = fmaxf(mt, s[r][c]);
            }
#pragma unroll
            for (int off = 1; off < 8; off <<= 1)
                mt = fmaxf(mt, __shfl_xor_sync(0xffffffffu, mt, off));

            const float mn   = fmaxf(m[r], mt);
            const float corr = __expf(m[r] - mn);
            float rs = 0.f;
#pragma unroll
            for (int c = 0; c < 8; c++) {
                const float pv = __expf(s[r][c] - mn);
                rs += pv;
                KtPt[tx * 8 + c][ty * 4 + r] = pv;
            }
#pragma unroll
            for (int off = 1; off < 8; off <<= 1)
                rs += __shfl_xor_sync(0xffffffffu, rs, off);

            l[r] = l[r] * corr + rs;
            m[r] = mn;
#pragma unroll
            for (int c = 0; c < 8; c++) o[r][c] *= corr;
        }
        __syncthreads();

#pragma unroll 4
        for (int j = 0; j < 64; j++) {
            float4 pa  = *(const float4*)&KtPt[j][ty * 4];
            float4 vb0 = *(const float4*)&Vs[j][tx * 8];
            float4 vb1 = *(const float4*)&Vs[j][tx * 8 + 4];
            float ra[4] = {pa.x, pa.y, pa.z, pa.w};
            float rbv[8] = {vb0.x, vb0.y, vb0.z, vb0.w, vb1.x, vb1.y, vb1.z, vb1.w};
#pragma unroll
            for (int r = 0; r < 4; r++)
#pragma unroll
                for (int c = 0; c < 8; c++)
                    o[r][c] += ra[r] * rbv[c];
        }
    }

#pragma unroll
    for (int r = 0; r < 4; r++) {
        const float inv = 1.f / l[r];
        const int row = i0 + ty * 4 + r;
        float* op = O + base + (size_t)row * HIDDEN + tx * 8;
#pragma unroll
        for (int c = 0; c < 8; c++) op[c] = o[r][c] * inv;
    }
}

/* ---------------- launch ------------------------------------------------- */
extern "C" void kernel_launch(void* const* d_in, const int* in_sizes, int n_in,
                              void* d_out, int out_size)
{
    (void)in_sizes; (void)n_in; (void)out_size;

    const float* query = (const float*)d_in[0];
    const float* value = (const float*)d_in[1];
    const float* Wq    = (const float*)d_in[2];
    const float* bq    = (const float*)d_in[3];
    const float* Wk    = (const float*)d_in[4];
    const float* bk    = (const float*)d_in[5];
    const float* Wv    = (const float*)d_in[6];
    const float* bv    = (const float*)d_in[7];
    const float* Wo    = (const float*)d_in[8];
    const float* bo    = (const float*)d_in[9];
    float* out = (float*)d_out;

    float *q, *k, *v, *ctx;
    cudaGetSymbolAddress((void**)&q,   g_q);
    cudaGetSymbolAddress((void**)&k,   g_k);
    cudaGetSymbolAddress((void**)&v,   g_v);
    cudaGetSymbolAddress((void**)&ctx, g_ctx);

    __nv_bfloat16 *qryhi, *qrylo, *valhi, *vallo, *ctxhi, *ctxlo, *whi, *wlo;
    cudaGetSymbolAddress((void**)&qryhi, g_qryhi);
    cudaGetSymbolAddress((void**)&qrylo, g_qrylo);
    cudaGetSymbolAddress((void**)&valhi, g_valhi);
    cudaGetSymbolAddress((void**)&vallo, g_vallo);
    cudaGetSymbolAddress((void**)&ctxhi, g_ctxhi);
    cudaGetSymbolAddress((void**)&ctxlo, g_ctxlo);
    cudaGetSymbolAddress((void**)&whi,   g_whi);
    cudaGetSymbolAddress((void**)&wlo,   g_wlo);

    const int nX4 = MTOT * HIDDEN / 4;     /* 2,097,152 */
    const int nW4 = HIDDEN * HIDDEN / 4;   /*   262,144 */

    split4_kernel<<<nX4 / 256, 256>>>((const float4*)query, (uint2*)qryhi, (uint2*)qrylo, nX4);
    split4_kernel<<<nX4 / 256, 256>>>((const float4*)value, (uint2*)valhi, (uint2*)vallo, nX4);
    split4_kernel<<<nW4 / 256, 256>>>((const float4*)Wq, (uint2*)(whi + 0 * HIDDEN * HIDDEN),
                                      (uint2*)(wlo + 0 * HIDDEN * HIDDEN), nW4);
    split4_kernel<<<nW4 / 256, 256>>>((const float4*)Wk, (uint2*)(whi + 1 * HIDDEN * HIDDEN),
                                      (uint2*)(wlo + 1 * HIDDEN * HIDDEN), nW4);
    split4_kernel<<<nW4 / 256, 256>>>((const float4*)Wv, (uint2*)(whi + 2 * HIDDEN * HIDDEN),
                                      (uint2*)(wlo + 2 * HIDDEN * HIDDEN), nW4);
    split4_kernel<<<nW4 / 256, 256>>>((const float4*)Wo, (uint2*)(whi + 3 * HIDDEN * HIDDEN),
                                      (uint2*)(wlo + 3 * HIDDEN * HIDDEN), nW4);

    dim3 gg(HIDDEN / 128, MTOT / 128);   /* (8, 64) */
    gemm_mma_kernel<<<gg, 256>>>(qryhi, qrylo,
                                 whi + 0 * HIDDEN * HIDDEN, wlo + 0 * HIDDEN * HIDDEN,
                                 bq, q);
    gemm_mma_kernel<<<gg, 256>>>(valhi, vallo,
                                 whi + 1 * HIDDEN * HIDDEN, wlo + 1 * HIDDEN * HIDDEN,
                                 bk, k);
    gemm_mma_kernel<<<gg, 256>>>(valhi, vallo,
                                 whi + 2 * HIDDEN * HIDDEN, wlo + 2 * HIDDEN * HIDDEN,
                                 bv, v);

    const int rope_threads = MTOT * HEADS * 16;
    rope_kernel<<<rope_threads / 256, 256>>>(q);
    rope_kernel<<<rope_threads / 256, 256>>>(k);

    attn_kernel<<<dim3(SEQ / 64, NB * HEADS), 128>>>(q, k, v, ctx);

    split4_kernel<<<nX4 / 256, 256>>>((const float4*)ctx, (uint2*)ctxhi, (uint2*)ctxlo, nX4);
    gemm_mma_kernel<<<gg, 256>>>(ctxhi, ctxlo,
                                 whi + 3 * HIDDEN * HIDDEN, wlo + 3 * HIDDEN * HIDDEN,
                                 bo, out);
}

// round 5
// speedup vs baseline: 3.1044x; 2.3742x over previous
#include <cuda_runtime.h>
#include <cuda_bf16.h>
#include <math.h>
#include <stdint.h>

#define HIDDEN 1024
#define HEADS  16
#define KD     64
#define NB     4
#define SEQ    2048
#define MTOT   (NB * SEQ)          /* 8192 rows */
#define SCALE  0.125f              /* 1/sqrt(64) */

/* ---------------- scratch (device globals: no allocs allowed) ------------- */
__device__ float g_q[MTOT * HIDDEN];
__device__ float g_k[MTOT * HIDDEN];
__device__ float g_v[MTOT * HIDDEN];
__device__ float g_ctx[MTOT * HIDDEN];

__device__ __nv_bfloat16 g_qryhi[MTOT * HIDDEN];
__device__ __nv_bfloat16 g_qrylo[MTOT * HIDDEN];
__device__ __nv_bfloat16 g_valhi[MTOT * HIDDEN];
__device__ __nv_bfloat16 g_vallo[MTOT * HIDDEN];
__device__ __nv_bfloat16 g_ctxhi[MTOT * HIDDEN];
__device__ __nv_bfloat16 g_ctxlo[MTOT * HIDDEN];
__device__ __nv_bfloat16 g_whi[4 * HIDDEN * HIDDEN];
__device__ __nv_bfloat16 g_wlo[4 * HIDDEN * HIDDEN];

/* attention operand buffers: [b,h,s,d] (q,k) and [b,h,d,s] (v transposed) */
__device__ __nv_bfloat16 g_qh[MTOT * HIDDEN];
__device__ __nv_bfloat16 g_ql[MTOT * HIDDEN];
__device__ __nv_bfloat16 g_kh[MTOT * HIDDEN];
__device__ __nv_bfloat16 g_kl[MTOT * HIDDEN];
__device__ __nv_bfloat16 g_vth[MTOT * HIDDEN];
__device__ __nv_bfloat16 g_vtl[MTOT * HIDDEN];

/* ======================= PTX helpers (sm_80-portable) ===================== */
__device__ __forceinline__ uint32_t smem_u32(const void* p) {
    uint32_t a;
    asm("{ .reg .u64 t; cvta.to.shared.u64 t, %1; cvt.u32.u64 %0, t; }"
        : "=r"(a) : "l"(p));
    return a;
}
__device__ __forceinline__ void cp16(uint32_t dst, const void* src) {
    asm volatile("cp.async.cg.shared.global [%0], [%1], 16;"
                 :: "r"(dst), "l"(src));
}
__device__ __forceinline__ void cp_commit() {
    asm volatile("cp.async.commit_group;" ::: "memory");
}
__device__ __forceinline__ void cp_wait0() {
    asm volatile("cp.async.wait_group 0;" ::: "memory");
}
__device__ __forceinline__ void cp_wait1() {
    asm volatile("cp.async.wait_group 1;" ::: "memory");
}
__device__ __forceinline__ void ldmx4(uint32_t* r, uint32_t a) {
    asm volatile("ldmatrix.sync.aligned.m8n8.x4.shared.b16 {%0,%1,%2,%3}, [%4];"
                 : "=r"(r[0]), "=r"(r[1]), "=r"(r[2]), "=r"(r[3]) : "r"(a));
}
__device__ __forceinline__ void mma_bf16(float* c, const uint32_t* a,
                                         uint32_t b0, uint32_t b1) {
    asm volatile(
        "mma.sync.aligned.m16n8k16.row.col.f32.bf16.bf16.f32 "
        "{%0,%1,%2,%3}, {%4,%5,%6,%7}, {%8,%9}, {%0,%1,%2,%3};"
        : "+f"(c[0]), "+f"(c[1]), "+f"(c[2]), "+f"(c[3])
        : "r"(a[0]), "r"(a[1]), "r"(a[2]), "r"(a[3]), "r"(b0), "r"(b1));
}

/* ======================= split fp32 -> (hi,lo) bf16 ======================= */
__global__ void split4_kernel(const float4* __restrict__ x,
                              uint2* __restrict__ hi, uint2* __restrict__ lo, int n4)
{
    int i = blockIdx.x * blockDim.x + threadIdx.x;
    if (i >= n4) return;
    float4 v = x[i];
    __nv_bfloat16 h0 = __float2bfloat16(v.x);
    __nv_bfloat16 h1 = __float2bfloat16(v.y);
    __nv_bfloat16 h2 = __float2bfloat16(v.z);
    __nv_bfloat16 h3 = __float2bfloat16(v.w);
    __nv_bfloat16 l0 = __float2bfloat16(v.x - __bfloat162float(h0));
    __nv_bfloat16 l1 = __float2bfloat16(v.y - __bfloat162float(h1));
    __nv_bfloat16 l2 = __float2bfloat16(v.z - __bfloat162float(h2));
    __nv_bfloat16 l3 = __float2bfloat16(v.w - __bfloat162float(h3));
    uint2 H, L;
    H.x = (uint32_t)__bfloat16_as_ushort(h0) | ((uint32_t)__bfloat16_as_ushort(h1) << 16);
    H.y = (uint32_t)__bfloat16_as_ushort(h2) | ((uint32_t)__bfloat16_as_ushort(h3) << 16);
    L.x = (uint32_t)__bfloat16_as_ushort(l0) | ((uint32_t)__bfloat16_as_ushort(l1) << 16);
    L.y = (uint32_t)__bfloat16_as_ushort(l2) | ((uint32_t)__bfloat16_as_ushort(l3) << 16);
    hi[i] = H;
    lo[i] = L;
}

/* ======================= mma.sync GEMM (bf16x3) =========================== */
#define ST    24
#define TILEB (128 * ST * 2)

__global__ __launch_bounds__(256)
void gemm_mma_kernel(const __nv_bfloat16* __restrict__ Ahi,
                     const __nv_bfloat16* __restrict__ Alo,
                     const __nv_bfloat16* __restrict__ Bhi,
                     const __nv_bfloat16* __restrict__ Blo,
                     const float* __restrict__ bias,
                     float* __restrict__ Y)
{
    __shared__ __align__(16) char sm[2 * 4 * TILEB];

    const int tid  = threadIdx.x;
    const int lane = tid & 31;
    const int warp = tid >> 5;
    const int wm   = warp >> 2;
    const int wn   = warp & 3;
    const int bm   = blockIdx.y * 128;
    const int bn   = blockIdx.x * 128;

    const uint32_t sb = smem_u32(sm);

    const __nv_bfloat16* srcs[4] = {
        Ahi + (size_t)bm * HIDDEN, Alo + (size_t)bm * HIDDEN,
        Bhi + (size_t)bn * HIDDEN, Blo + (size_t)bn * HIDDEN
    };

    const int lrow  = tid >> 1;
    const int lpart = tid & 1;

#define LOAD_STAGE(s, k0)                                                     \
    do {                                                                      \
        _Pragma("unroll")                                                     \
        for (int t = 0; t < 4; t++) {                                         \
            uint32_t dst = sb + ((s) * 4 + t) * TILEB + lrow * 48 + lpart * 16; \
            const char* src = (const char*)(srcs[t] + (size_t)lrow * HIDDEN + (k0)) \
                              + lpart * 16;                                   \
            cp16(dst, src);                                                   \
        }                                                                     \
        cp_commit();                                                          \
    } while (0)

    float acc[4][4][4];
#pragma unroll
    for (int mi = 0; mi < 4; mi++)
#pragma unroll
        for (int ni = 0; ni < 4; ni++)
#pragma unroll
            for (int e = 0; e < 4; e++) acc[mi][ni][e] = 0.f;

    LOAD_STAGE(0, 0);

    const int arow  = wm * 64 + (lane & 15);
    const int acolb = (lane >> 4) << 4;
    const int brow  = wn * 32 + (lane & 7) + ((lane >> 4) << 3);
    const int bcolb = ((lane >> 3) & 1) << 4;

    for (int ck = 0; ck < HIDDEN / 16; ck++) {
        if (ck < HIDDEN / 16 - 1) {
            LOAD_STAGE((ck + 1) & 1, (ck + 1) * 16);
            cp_wait1();
        } else {
            cp_wait0();
        }
        __syncthreads();

        const uint32_t base = sb + (ck & 1) * 4 * TILEB;
        const uint32_t aHiB = base;
        const uint32_t aLoB = base + TILEB;
        const uint32_t bHiB = base + 2 * TILEB;
        const uint32_t bLoB = base + 3 * TILEB;

        uint32_t ah[4][4], al[4][4], bh[2][4], bl[2][4];
#pragma unroll
        for (int mi = 0; mi < 4; mi++) {
            ldmx4(ah[mi], aHiB + (arow + mi * 16) * 48 + acolb);
            ldmx4(al[mi], aLoB + (arow + mi * 16) * 48 + acolb);
        }
#pragma unroll
        for (int nb = 0; nb < 2; nb++) {
            ldmx4(bh[nb], bHiB + (brow + nb * 16) * 48 + bcolb);
            ldmx4(bl[nb], bLoB + (brow + nb * 16) * 48 + bcolb);
        }

#pragma unroll
        for (int mi = 0; mi < 4; mi++)
#pragma unroll
            for (int ni = 0; ni < 4; ni++) {
                const int nb = ni >> 1, o = (ni & 1) * 2;
                mma_bf16(acc[mi][ni], ah[mi], bh[nb][o], bh[nb][o + 1]);
                mma_bf16(acc[mi][ni], ah[mi], bl[nb][o], bl[nb][o + 1]);
                mma_bf16(acc[mi][ni], al[mi], bh[nb][o], bh[nb][o + 1]);
            }

        __syncthreads();
    }

#pragma unroll
    for (int ni = 0; ni < 4; ni++) {
        const int col = bn + wn * 32 + ni * 8 + (lane & 3) * 2;
        const float b0 = bias[col], b1 = bias[col + 1];
#pragma unroll
        for (int mi = 0; mi < 4; mi++) {
            const int row = bm + wm * 64 + mi * 16 + (lane >> 2);
            float2 v0 = make_float2(acc[mi][ni][0] + b0, acc[mi][ni][1] + b1);
            float2 v1 = make_float2(acc[mi][ni][2] + b0, acc[mi][ni][3] + b1);
            *(float2*)&Y[(size_t)row * HIDDEN + col]       = v0;
            *(float2*)&Y[(size_t)(row + 8) * HIDDEN + col] = v1;
        }
    }
#undef LOAD_STAGE
}

/* ============ RoPE + split:  g_q/g_k fp32 -> [b,h,s,d] bf16 hi/lo ========= */
__global__ void qk_rope_split_kernel(const float* __restrict__ X,
                                     __nv_bfloat16* __restrict__ hi,
                                     __nv_bfloat16* __restrict__ lo)
{
    const int idx = blockIdx.x * blockDim.x + threadIdx.x;   /* MTOT*1024 */
    const int d    = idx & 63;
    const int hcol = (idx >> 6) & 15;
    const int row  = idx >> 10;
    const int s    = row & (SEQ - 1);
    const int b    = row >> 11;

    float x = X[idx];
    float val;
    if (d < 32) {
        const int t = d & 15;
        const float theta = powf(10000.f, -(float)t * (1.f / 16.f));
        const float ang   = (float)s * theta;
        float si, c;
        sincosf(ang, &si, &c);
        const float partner = X[idx ^ 16];
        val = (d < 16) ? (x * c - partner * si) : (x * c + partner * si);
    } else {
        val = x;
    }

    const __nv_bfloat16 h = __float2bfloat16(val);
    const __nv_bfloat16 l = __float2bfloat16(val - __bfloat162float(h));
    const size_t oidx = (((size_t)(b * HEADS + hcol)) * SEQ + s) * 64 + d;
    hi[oidx] = h;
    lo[oidx] = l;
}

/* ============ V split + transpose: g_v fp32 -> [b,h,d,s] bf16 hi/lo ======= */
__global__ __launch_bounds__(256)
void v_split_t_kernel(const float* __restrict__ V,
                      __nv_bfloat16* __restrict__ hi,
                      __nv_bfloat16* __restrict__ lo)
{
    __shared__ float tile[64][65];
    const int tid = threadIdx.x;
    const int s0  = blockIdx.x * 64;
    const int bh  = blockIdx.y;
    const int b   = bh >> 4;
    const int h   = bh & 15;

    /* read 64 s x 64 d */
    {
        const int d = tid & 63, sg = tid >> 6;
#pragma unroll
        for (int r = 0; r < 16; r++) {
            const int s = sg * 16 + r;
            tile[s][d] = V[((size_t)(b * SEQ + s0 + s)) * HIDDEN + h * 64 + d];
        }
    }
    __syncthreads();

    /* write rows d, cols s (pairs) */
    {
        const int d = tid >> 2, sg = tid & 3;
        const size_t obase = ((size_t)(bh * 64 + d)) * SEQ + s0 + sg * 16;
#pragma unroll
        for (int r = 0; r < 16; r += 2) {
            const float v0 = tile[sg * 16 + r][d];
            const float v1 = tile[sg * 16 + r + 1][d];
            const __nv_bfloat16 h0 = __float2bfloat16(v0);
            const __nv_bfloat16 h1 = __float2bfloat16(v1);
            __nv_bfloat162 H; H.x = h0; H.y = h1;
            __nv_bfloat162 L;
            L.x = __float2bfloat16(v0 - __bfloat162float(h0));
            L.y = __float2bfloat16(v1 - __bfloat162float(h1));
            *(__nv_bfloat162*)&hi[obase + r] = H;
            *(__nv_bfloat162*)&lo[obase + r] = L;
        }
    }
}

/* ======================= mma.sync flash attention ========================= *
 * Grid (SEQ/128, NB*HEADS), 256 thr = 8 warps; warp owns 16 q-rows.
 * Bc = 64 K/V columns per iteration, double-buffered cp.async.
 * S = QK^T (bf16x3), online softmax in regs, P repacked in regs, O += P V (bf16x3).
 */
#define ASTR   144                      /* 64 bf16 + 8 pad = 144 B row */
#define ATILE  (64 * ASTR)              /* 9216 B */
#define AQ     (128 * ASTR)             /* 18432 B */
#define ASMEM  (2 * AQ + 2 * 4 * ATILE) /* 110592 B */

__global__ __launch_bounds__(256)
void attn_mma_kernel(const __nv_bfloat16* __restrict__ qh, const __nv_bfloat16* __restrict__ ql,
                     const __nv_bfloat16* __restrict__ kh, const __nv_bfloat16* __restrict__ kl,
                     const __nv_bfloat16* __restrict__ vth, const __nv_bfloat16* __restrict__ vtl,
                     float* __restrict__ O)
{
    extern __shared__ __align__(16) char sm[];
    const uint32_t sb = smem_u32(sm);
    const int tid  = threadIdx.x;
    const int lane = tid & 31;
    const int warp = tid >> 5;
    const int bh   = blockIdx.y;
    const int b    = bh >> 4;
    const int i0   = blockIdx.x * 128;

    const uint32_t sQH = sb;
    const uint32_t sQL = sb + AQ;
    const uint32_t sKV = sb + 2 * AQ;

    /* ---- prologue loads: Q tiles + KV iter0 ---- */
    {
        const int r = tid >> 3, ch = tid & 7;
        const size_t qbase = ((size_t)bh * SEQ + i0) * 64;
#pragma unroll
        for (int k4 = 0; k4 < 4; k4++) {
            const int row = r + k4 * 32;
            cp16(sQH + row * ASTR + ch * 16, qh + qbase + (size_t)row * 64 + ch * 8);
            cp16(sQL + row * ASTR + ch * 16, ql + qbase + (size_t)row * 64 + ch * 8);
        }
    }

#define ATT_LOAD(buf, j0)                                                        \
    do {                                                                         \
        const int r_ = tid >> 3, ch_ = tid & 7;                                  \
        const uint32_t kb_ = sKV + (buf) * 4 * ATILE;                            \
        _Pragma("unroll")                                                        \
        for (int hf = 0; hf < 2; hf++) {                                         \
            const int row = r_ + hf * 32;                                        \
            const size_t ks = ((size_t)bh * SEQ + (j0) + row) * 64 + ch_ * 8;    \
            const size_t vs = ((size_t)bh * 64 + row) * SEQ + (j0) + ch_ * 8;    \
            cp16(kb_ + 0 * ATILE + row * ASTR + ch_ * 16, kh + ks);              \
            cp16(kb_ + 1 * ATILE + row * ASTR + ch_ * 16, kl + ks);              \
            cp16(kb_ + 2 * ATILE + row * ASTR + ch_ * 16, vth + vs);             \
            cp16(kb_ + 3 * ATILE + row * ASTR + ch_ * 16, vtl + vs);             \
        }                                                                        \
        cp_commit();                                                             \
    } while (0)

    ATT_LOAD(0, 0);

    float m0 = -1e30f, m1 = -1e30f, l0 = 0.f, l1 = 0.f;
    float o[8][4];
#pragma unroll
    for (int n = 0; n < 8; n++)
#pragma unroll
        for (int e = 0; e < 4; e++) o[n][e] = 0.f;

    uint32_t qfh[4][4], qfl[4][4];

    const int frow  = (lane & 7) + ((lane >> 4) << 3);
    const int fcolb = ((lane >> 3) & 1) << 4;

    for (int it = 0; it < SEQ / 64; it++) {
        if (it + 1 < SEQ / 64) {
            ATT_LOAD((it + 1) & 1, (it + 1) * 64);
            cp_wait1();
        } else {
            cp_wait0();
        }
        __syncthreads();

        if (it == 0) {
            /* build Q frags once (Q arrived with group 0) */
            const int arow  = warp * 16 + (lane & 15);
            const int acolb = (lane >> 4) << 4;
#pragma unroll
            for (int kc = 0; kc < 4; kc++) {
                ldmx4(qfh[kc], sQH + arow * ASTR + kc * 32 + acolb);
                ldmx4(qfl[kc], sQL + arow * ASTR + kc * 32 + acolb);
            }
        }

        const uint32_t kb  = sKV + (it & 1) * 4 * ATILE;
        const uint32_t kHb = kb, kLb = kb + ATILE;
        const uint32_t vHb = kb + 2 * ATILE, vLb = kb + 3 * ATILE;

        /* ---- S = Q K^T ---- */
        float s[8][4];
#pragma unroll
        for (int n = 0; n < 8; n++)
#pragma unroll
            for (int e = 0; e < 4; e++) s[n][e] = 0.f;

#pragma unroll
        for (int kc = 0; kc < 4; kc++) {
#pragma unroll
            for (int nb = 0; nb < 4; nb++) {
                uint32_t bhf[4], blf[4];
                ldmx4(bhf, kHb + (nb * 16 + frow) * ASTR + kc * 32 + fcolb);
                ldmx4(blf, kLb + (nb * 16 + frow) * ASTR + kc * 32 + fcolb);
#pragma unroll
                for (int o2 = 0; o2 < 2; o2++) {
                    const int n = nb * 2 + o2;
                    mma_bf16(s[n], qfh[kc], bhf[o2 * 2], bhf[o2 * 2 + 1]);
                    mma_bf16(s[n], qfh[kc], blf[o2 * 2], blf[o2 * 2 + 1]);
                    mma_bf16(s[n], qfl[kc], bhf[o2 * 2], bhf[o2 * 2 + 1]);
                }
            }
        }

        /* ---- online softmax (rows r and r+8) ---- */
        float mx0 = -1e30f, mx1 = -1e30f;
#pragma unroll
        for (int n = 0; n < 8; n++) {
            mx0 = fmaxf(mx0, fmaxf(s[n][0], s[n][1]));
            mx1 = fmaxf(mx1, fmaxf(s[n][2], s[n][3]));
        }
        mx0 = fmaxf(mx0, __shfl_xor_sync(0xffffffffu, mx0, 1));
        mx0 = fmaxf(mx0, __shfl_xor_sync(0xffffffffu, mx0, 2));
        mx1 = fmaxf(mx1, __shfl_xor_sync(0xffffffffu, mx1, 1));
        mx1 = fmaxf(mx1, __shfl_xor_sync(0xffffffffu, mx1, 2));

        const float mn0 = fmaxf(m0, mx0 * SCALE);
        const float mn1 = fmaxf(m1, mx1 * SCALE);
        const float c0 = __expf(m0 - mn0);
        const float c1 = __expf(m1 - mn1);

        float rs0 = 0.f, rs1 = 0.f;
#pragma unroll
        for (int n = 0; n < 8; n++) {
            s[n][0] = __expf(fmaf(s[n][0], SCALE, -mn0)); rs0 += s[n][0];
            s[n][1] = __expf(fmaf(s[n][1], SCALE, -mn0)); rs0 += s[n][1];
            s[n][2] = __expf(fmaf(s[n][2], SCALE, -mn1)); rs1 += s[n][2];
            s[n][3] = __expf(fmaf(s[n][3], SCALE, -mn1)); rs1 += s[n][3];
        }
        rs0 += __shfl_xor_sync(0xffffffffu, rs0, 1);
        rs0 += __shfl_xor_sync(0xffffffffu, rs0, 2);
        rs1 += __shfl_xor_sync(0xffffffffu, rs1, 1);
        rs1 += __shfl_xor_sync(0xffffffffu, rs1, 2);

        l0 = l0 * c0 + rs0;  l1 = l1 * c1 + rs1;
        m0 = mn0;            m1 = mn1;

#pragma unroll
        for (int n = 0; n < 8; n++) {
            o[n][0] *= c0; o[n][1] *= c0;
            o[n][2] *= c1; o[n][3] *= c1;
        }

        /* ---- O += P V (P repacked in regs as A-frags) ---- */
#pragma unroll
        for (int kc = 0; kc < 4; kc++) {
            uint32_t afh[4], afl[4];
#pragma unroll
            for (int q2 = 0; q2 < 2; q2++) {       /* q2: k-halves (ntile 2kc+q2) */
                const int n = 2 * kc + q2;
#pragma unroll
                for (int rh = 0; rh < 2; rh++) {   /* rh: row r / r+8 */
                    const float p0 = s[n][rh * 2 + 0];
                    const float p1 = s[n][rh * 2 + 1];
                    __nv_bfloat162 H = __float22bfloat162_rn(make_float2(p0, p1));
                    float2 hf = __bfloat1622float2(H);
                    __nv_bfloat162 L = __float22bfloat162_rn(make_float2(p0 - hf.x, p1 - hf.y));
                    afh[q2 * 2 + rh] = *(uint32_t*)&H;
                    afl[q2 * 2 + rh] = *(uint32_t*)&L;
                }
            }
#pragma unroll
            for (int nb = 0; nb < 4; nb++) {
                uint32_t vh4[4], vl4[4];
                ldmx4(vh4, vHb + (nb * 16 + frow) * ASTR + kc * 32 + fcolb);
                ldmx4(vl4, vLb + (nb * 16 + frow) * ASTR + kc * 32 + fcolb);
#pragma unroll
                for (int o2 = 0; o2 < 2; o2++) {
                    const int n = nb * 2 + o2;
                    mma_bf16(o[n], afh, vh4[o2 * 2], vh4[o2 * 2 + 1]);
                    mma_bf16(o[n], afh, vl4[o2 * 2], vl4[o2 * 2 + 1]);
                    mma_bf16(o[n], afl, vh4[o2 * 2], vh4[o2 * 2 + 1]);
                }
            }
        }

        __syncthreads();
    }

    /* ---- epilogue: normalize, write fp32 ctx [b, i, h*64+d] ---- */
    const float inv0 = 1.f / l0;
    const float inv1 = 1.f / l1;
    const int r1 = i0 + warp * 16 + (lane >> 2);
    const int h  = bh & 15;
#pragma unroll
    for (int n = 0; n < 8; n++) {
        const int col = h * 64 + n * 8 + (lane & 3) * 2;
        float2 v0 = make_float2(o[n][0] * inv0, o[n][1] * inv0);
        float2 v1 = make_float2(o[n][2] * inv1, o[n][3] * inv1);
        *(float2*)&O[((size_t)(b * SEQ + r1)) * HIDDEN + col]     = v0;
        *(float2*)&O[((size_t)(b * SEQ + r1 + 8)) * HIDDEN + col] = v1;
    }
#undef ATT_LOAD
}

/* ---------------- launch ------------------------------------------------- */
extern "C" void kernel_launch(void* const* d_in, const int* in_sizes, int n_in,
                              void* d_out, int out_size)
{
    (void)in_sizes; (void)n_in; (void)out_size;

    const float* query = (const float*)d_in[0];
    const float* value = (const float*)d_in[1];
    const float* Wq    = (const float*)d_in[2];
    const float* bq    = (const float*)d_in[3];
    const float* Wk    = (const float*)d_in[4];
    const float* bk    = (const float*)d_in[5];
    const float* Wv    = (const float*)d_in[6];
    const float* bv    = (const float*)d_in[7];
    const float* Wo    = (const float*)d_in[8];
    const float* bo    = (const float*)d_in[9];
    float* out = (float*)d_out;

    float *q, *k, *v, *ctx;
    cudaGetSymbolAddress((void**)&q,   g_q);
    cudaGetSymbolAddress((void**)&k,   g_k);
    cudaGetSymbolAddress((void**)&v,   g_v);
    cudaGetSymbolAddress((void**)&ctx, g_ctx);

    __nv_bfloat16 *qryhi, *qrylo, *valhi, *vallo, *ctxhi, *ctxlo, *whi, *wlo;
    __nv_bfloat16 *qhp, *qlp, *khp, *klp, *vthp, *vtlp;
    cudaGetSymbolAddress((void**)&qryhi, g_qryhi);
    cudaGetSymbolAddress((void**)&qrylo, g_qrylo);
    cudaGetSymbolAddress((void**)&valhi, g_valhi);
    cudaGetSymbolAddress((void**)&vallo, g_vallo);
    cudaGetSymbolAddress((void**)&ctxhi, g_ctxhi);
    cudaGetSymbolAddress((void**)&ctxlo, g_ctxlo);
    cudaGetSymbolAddress((void**)&whi,   g_whi);
    cudaGetSymbolAddress((void**)&wlo,   g_wlo);
    cudaGetSymbolAddress((void**)&qhp,  g_qh);
    cudaGetSymbolAddress((void**)&qlp,  g_ql);
    cudaGetSymbolAddress((void**)&khp,  g_kh);
    cudaGetSymbolAddress((void**)&klp,  g_kl);
    cudaGetSymbolAddress((void**)&vthp, g_vth);
    cudaGetSymbolAddress((void**)&vtlp, g_vtl);

    cudaFuncSetAttribute(attn_mma_kernel,
                         cudaFuncAttributeMaxDynamicSharedMemorySize, ASMEM);

    const int nX4 = MTOT * HIDDEN / 4;
    const int nW4 = HIDDEN * HIDDEN / 4;

    split4_kernel<<<nX4 / 256, 256>>>((const float4*)query, (uint2*)qryhi, (uint2*)qrylo, nX4);
    split4_kernel<<<nX4 / 256, 256>>>((const float4*)value, (uint2*)valhi, (uint2*)vallo, nX4);
    split4_kernel<<<nW4 / 256, 256>>>((const float4*)Wq, (uint2*)(whi + 0 * HIDDEN * HIDDEN),
                                      (uint2*)(wlo + 0 * HIDDEN * HIDDEN), nW4);
    split4_kernel<<<nW4 / 256, 256>>>((const float4*)Wk, (uint2*)(whi + 1 * HIDDEN * HIDDEN),
                                      (uint2*)(wlo + 1 * HIDDEN * HIDDEN), nW4);
    split4_kernel<<<nW4 / 256, 256>>>((const float4*)Wv, (uint2*)(whi + 2 * HIDDEN * HIDDEN),
                                      (uint2*)(wlo + 2 * HIDDEN * HIDDEN), nW4);
    split4_kernel<<<nW4 / 256, 256>>>((const float4*)Wo, (uint2*)(whi + 3 * HIDDEN * HIDDEN),
                                      (uint2*)(wlo + 3 * HIDDEN * HIDDEN), nW4);

    dim3 gg(HIDDEN / 128, MTOT / 128);
    gemm_mma_kernel<<<gg, 256>>>(qryhi, qrylo,
                                 whi + 0 * HIDDEN * HIDDEN, wlo + 0 * HIDDEN * HIDDEN,
                                 bq, q);
    gemm_mma_kernel<<<gg, 256>>>(valhi, vallo,
                                 whi + 1 * HIDDEN * HIDDEN, wlo + 1 * HIDDEN * HIDDEN,
                                 bk, k);
    gemm_mma_kernel<<<gg, 256>>>(valhi, vallo,
                                 whi + 2 * HIDDEN * HIDDEN, wlo + 2 * HIDDEN * HIDDEN,
                                 bv, v);

    const int nQK = MTOT * HIDDEN;
    qk_rope_split_kernel<<<nQK / 256, 256>>>(q, qhp, qlp);
    qk_rope_split_kernel<<<nQK / 256, 256>>>(k, khp, klp);
    v_split_t_kernel<<<dim3(SEQ / 64, NB * HEADS), 256>>>(v, vthp, vtlp);

    attn_mma_kernel<<<dim3(SEQ / 128, NB * HEADS), 256, ASMEM>>>(
        qhp, qlp, khp, klp, vthp, vtlp, ctx);

    split4_kernel<<<nX4 / 256, 256>>>((const float4*)ctx, (uint2*)ctxhi, (uint2*)ctxlo, nX4);
    gemm_mma_kernel<<<gg, 256>>>(ctxhi, ctxlo,
                                 whi + 3 * HIDDEN * HIDDEN, wlo + 3 * HIDDEN * HIDDEN,
                                 bo, out);
}

// round 8
// speedup vs baseline: 6.9810x; 2.2488x over previous
#include <cuda_runtime.h>
#include <cuda_fp16.h>
#include <math.h>
#include <stdint.h>

#define HIDDEN 1024
#define HEADS  16
#define KD     64
#define NB     4
#define SEQ    2048
#define MTOT   (NB * SEQ)          /* 8192 rows */
#define SCALE  0.125f              /* 1/sqrt(64) */

/* ---------------- scratch (device globals: no allocs allowed) ------------- */
__device__ float g_q[MTOT * HIDDEN];
__device__ float g_k[MTOT * HIDDEN];
__device__ float g_v[MTOT * HIDDEN];
__device__ float g_ctx[MTOT * HIDDEN];

__device__ __half g_qryh[MTOT * HIDDEN];
__device__ __half g_valh[MTOT * HIDDEN];
__device__ __half g_ctxh[MTOT * HIDDEN];
__device__ __half g_wh[4 * HIDDEN * HIDDEN];

/* attention operands: [b,h,s,d] (q,k) and [b,h,d,s] (v transposed) */
__device__ __half g_qh[MTOT * HIDDEN];
__device__ __half g_kh[MTOT * HIDDEN];
__device__ __half g_vth[MTOT * HIDDEN];

/* ======================= PTX helpers (sm_80-portable) ===================== */
__device__ __forceinline__ uint32_t smem_u32(const void* p) {
    uint32_t a;
    asm("{ .reg .u64 t; cvta.to.shared.u64 t, %1; cvt.u32.u64 %0, t; }"
        : "=r"(a) : "l"(p));
    return a;
}
__device__ __forceinline__ void cp16(uint32_t dst, const void* src) {
    asm volatile("cp.async.cg.shared.global [%0], [%1], 16;"
                 :: "r"(dst), "l"(src));
}
__device__ __forceinline__ void cp_commit() {
    asm volatile("cp.async.commit_group;" ::: "memory");
}
__device__ __forceinline__ void cp_wait0() {
    asm volatile("cp.async.wait_group 0;" ::: "memory");
}
__device__ __forceinline__ void cp_wait1() {
    asm volatile("cp.async.wait_group 1;" ::: "memory");
}
__device__ __forceinline__ void ldmx4(uint32_t* r, uint32_t a) {
    asm volatile("ldmatrix.sync.aligned.m8n8.x4.shared.b16 {%0,%1,%2,%3}, [%4];"
                 : "=r"(r[0]), "=r"(r[1]), "=r"(r[2]), "=r"(r[3]) : "r"(a));
}
__device__ __forceinline__ void mma_fp16(float* c, const uint32_t* a,
                                         uint32_t b0, uint32_t b1) {
    asm volatile(
        "mma.sync.aligned.m16n8k16.row.col.f32.f16.f16.f32 "
        "{%0,%1,%2,%3}, {%4,%5,%6,%7}, {%8,%9}, {%0,%1,%2,%3};"
        : "+f"(c[0]), "+f"(c[1]), "+f"(c[2]), "+f"(c[3])
        : "r"(a[0]), "r"(a[1]), "r"(a[2]), "r"(a[3]), "r"(b0), "r"(b1));
}

/* ======================= cvt fp32 -> fp16 ================================= */
__global__ void cvt4_kernel(const float4* __restrict__ x,
                            uint2* __restrict__ out, int n4)
{
    int i = blockIdx.x * blockDim.x + threadIdx.x;
    if (i >= n4) return;
    float4 v = x[i];
    __half2 h0 = __float22half2_rn(make_float2(v.x, v.y));
    __half2 h1 = __float22half2_rn(make_float2(v.z, v.w));
    uint2 o;
    o.x = *(uint32_t*)&h0;
    o.y = *(uint32_t*)&h1;
    out[i] = o;
}

/* ======================= mma.sync GEMM (fp16) ============================= *
 * Y[M,N] = A[M,K] @ B[N,K]^T + bias, fp32 out.
 * CTA 128x128, 8 warps (2m x 4n), warp tile 64x32, K-chunk 32 (= 64 B rows),
 * 2-stage cp.async, 40 KB static smem.
 */
#define GST   80                  /* row stride: 64 B data + 16 B pad */
#define GTILE (128 * GST)         /* 10240 B per tile */

__global__ __launch_bounds__(256)
void gemm_fp16_kernel(const __half* __restrict__ A,
                      const __half* __restrict__ B,
                      const float* __restrict__ bias,
                      float* __restrict__ Y)
{
    __shared__ __align__(16) char sm[2 * 2 * GTILE];   /* 40960 B */

    const int tid  = threadIdx.x;
    const int lane = tid & 31;
    const int warp = tid >> 5;
    const int wm   = warp >> 2;
    const int wn   = warp & 3;
    const int bm   = blockIdx.y * 128;
    const int bn   = blockIdx.x * 128;

    const uint32_t sb = smem_u32(sm);
    const __half* srcA = A + (size_t)bm * HIDDEN;
    const __half* srcB = B + (size_t)bn * HIDDEN;

    const int lrow = tid >> 1;           /* 0..127 */
    const int lhalf = tid & 1;           /* 0..1 : which 32B half of the 64B row */

#define G_LOAD(s, k0)                                                          \
    do {                                                                       \
        uint32_t dA = sb + (s) * 2 * GTILE + lrow * GST + lhalf * 32;          \
        uint32_t dB = dA + GTILE;                                              \
        const __half* pa = srcA + (size_t)lrow * HIDDEN + (k0) + lhalf * 16;   \
        const __half* pb = srcB + (size_t)lrow * HIDDEN + (k0) + lhalf * 16;   \
        cp16(dA, pa);      cp16(dA + 16, pa + 8);                              \
        cp16(dB, pb);      cp16(dB + 16, pb + 8);                              \
        cp_commit();                                                           \
    } while (0)

    float acc[4][4][4];
#pragma unroll
    for (int mi = 0; mi < 4; mi++)
#pragma unroll
        for (int ni = 0; ni < 4; ni++)
#pragma unroll
            for (int e = 0; e < 4; e++) acc[mi][ni][e] = 0.f;

    G_LOAD(0, 0);

    const int arow  = wm * 64 + (lane & 15);
    const int acolb = (lane >> 4) << 4;
    const int brow  = wn * 32 + (lane & 7) + ((lane >> 4) << 3);
    const int bcolb = ((lane >> 3) & 1) << 4;

    for (int ck = 0; ck < HIDDEN / 32; ck++) {
        if (ck < HIDDEN / 32 - 1) {
            G_LOAD((ck + 1) & 1, (ck + 1) * 32);
            cp_wait1();
        } else {
            cp_wait0();
        }
        __syncthreads();

        const uint32_t aB = sb + (ck & 1) * 2 * GTILE;
        const uint32_t bB = aB + GTILE;

        uint32_t af[2][4][4], bf[2][2][4];
#pragma unroll
        for (int kc = 0; kc < 2; kc++) {
#pragma unroll
            for (int mi = 0; mi < 4; mi++)
                ldmx4(af[kc][mi], aB + (arow + mi * 16) * GST + kc * 32 + acolb);
#pragma unroll
            for (int nb = 0; nb < 2; nb++)
                ldmx4(bf[kc][nb], bB + (brow + nb * 16) * GST + kc * 32 + bcolb);
        }

#pragma unroll
        for (int kc = 0; kc < 2; kc++)
#pragma unroll
            for (int mi = 0; mi < 4; mi++)
#pragma unroll
                for (int ni = 0; ni < 4; ni++) {
                    const int nb = ni >> 1, o = (ni & 1) * 2;
                    mma_fp16(acc[mi][ni], af[kc][mi], bf[kc][nb][o], bf[kc][nb][o + 1]);
                }

        __syncthreads();
    }

#pragma unroll
    for (int ni = 0; ni < 4; ni++) {
        const int col = bn + wn * 32 + ni * 8 + (lane & 3) * 2;
        const float b0 = bias[col], b1 = bias[col + 1];
#pragma unroll
        for (int mi = 0; mi < 4; mi++) {
            const int row = bm + wm * 64 + mi * 16 + (lane >> 2);
            float2 v0 = make_float2(acc[mi][ni][0] + b0, acc[mi][ni][1] + b1);
            float2 v1 = make_float2(acc[mi][ni][2] + b0, acc[mi][ni][3] + b1);
            *(float2*)&Y[(size_t)row * HIDDEN + col]       = v0;
            *(float2*)&Y[(size_t)(row + 8) * HIDDEN + col] = v1;
        }
    }
#undef G_LOAD
}

/* ============ RoPE + cvt:  fp32 [b,s,h,d] -> fp16 [b,h,s,d] =============== */
__global__ void qk_rope_cvt_kernel(const float* __restrict__ X,
                                   __half* __restrict__ out)
{
    const int idx = blockIdx.x * blockDim.x + threadIdx.x;   /* MTOT*1024 */
    const int d    = idx & 63;
    const int hcol = (idx >> 6) & 15;
    const int row  = idx >> 10;
    const int s    = row & (SEQ - 1);
    const int b    = row >> 11;

    float x = X[idx];
    float val;
    if (d < 32) {
        const int t = d & 15;
        const float theta = powf(10000.f, -(float)t * (1.f / 16.f));
        const float ang   = (float)s * theta;
        float si, c;
        sincosf(ang, &si, &c);
        const float partner = X[idx ^ 16];
        val = (d < 16) ? (x * c - partner * si) : (x * c + partner * si);
    } else {
        val = x;
    }

    const size_t oidx = (((size_t)(b * HEADS + hcol)) * SEQ + s) * 64 + d;
    out[oidx] = __float2half_rn(val);
}

/* ============ V cvt + transpose: fp32 -> fp16 [b,h,d,s] =================== */
__global__ __launch_bounds__(256)
void v_cvt_t_kernel(const float* __restrict__ V, __half* __restrict__ out)
{
    __shared__ float tile[64][65];
    const int tid = threadIdx.x;
    const int s0  = blockIdx.x * 64;
    const int bh  = blockIdx.y;
    const int b   = bh >> 4;
    const int h   = bh & 15;

    {
        const int d = tid & 63, sg = tid >> 6;
#pragma unroll
        for (int r = 0; r < 16; r++) {
            const int s = sg * 16 + r;
            tile[s][d] = V[((size_t)(b * SEQ + s0 + s)) * HIDDEN + h * 64 + d];
        }
    }
    __syncthreads();

    {
        const int d = tid >> 2, sg = tid & 3;
        const size_t obase = ((size_t)(bh * 64 + d)) * SEQ + s0 + sg * 16;
#pragma unroll
        for (int r = 0; r < 16; r += 2) {
            __half2 H = __float22half2_rn(
                make_float2(tile[sg * 16 + r][d], tile[sg * 16 + r + 1][d]));
            *(__half2*)&out[obase + r] = H;
        }
    }
}

/* ======================= mma.sync flash attention (fp16) ================== *
 * Grid (SEQ/128, NB*HEADS), 256 thr = 8 warps; warp owns 16 q-rows.
 * Bc = 64 per iter, double-buffered cp.async.
 * Rows are 64 fp16 = 128 B data; ASTR = 144 (16 B pad) — R5-validated layout.
 * smem: Q 18432 + 2 stages x (K+V) x 9216 = 55296 B (dynamic).
 */
#define ASTR   144
#define ATILE  (64 * ASTR)              /* 9216 B */
#define AQ     (128 * ASTR)             /* 18432 B */
#define ASMEM  (AQ + 2 * 2 * ATILE)     /* 55296 B */

__global__ __launch_bounds__(256)
void attn_fp16_kernel(const __half* __restrict__ qh,
                      const __half* __restrict__ kh,
                      const __half* __restrict__ vth,
                      float* __restrict__ O)
{
    extern __shared__ __align__(16) char sm[];
    const uint32_t sb = smem_u32(sm);
    const int tid  = threadIdx.x;
    const int lane = tid & 31;
    const int warp = tid >> 5;
    const int bh   = blockIdx.y;
    const int b    = bh >> 4;
    const int i0   = blockIdx.x * 128;

    const uint32_t sQ  = sb;
    const uint32_t sKV = sb + AQ;

    /* ---- prologue: Q tile (128 rows x 128 B), folds into group 0 ---- */
    {
        const int r = tid >> 3, ch = tid & 7;            /* r 0..31, ch 0..7 */
        const size_t qbase = ((size_t)bh * SEQ + i0) * 64;
#pragma unroll
        for (int k4 = 0; k4 < 4; k4++) {
            const int row = r + k4 * 32;
            cp16(sQ + row * ASTR + ch * 16, qh + qbase + (size_t)row * 64 + ch * 8);
        }
    }

#define ATT_LOAD(buf, j0)                                                       \
    do {                                                                        \
        const int r_ = tid >> 3, ch_ = tid & 7;                                 \
        const uint32_t kb_ = sKV + (buf) * 2 * ATILE;                           \
        _Pragma("unroll")                                                       \
        for (int hf = 0; hf < 2; hf++) {                                        \
            const int row = r_ + hf * 32;                                       \
            const size_t ks = ((size_t)bh * SEQ + (j0) + row) * 64 + ch_ * 8;   \
            const size_t vs = ((size_t)bh * 64 + row) * SEQ + (j0) + ch_ * 8;   \
            cp16(kb_ + row * ASTR + ch_ * 16,         kh + ks);                 \
            cp16(kb_ + ATILE + row * ASTR + ch_ * 16, vth + vs);                \
        }                                                                       \
        cp_commit();                                                            \
    } while (0)

    ATT_LOAD(0, 0);

    float m0 = -1e30f, m1 = -1e30f, l0 = 0.f, l1 = 0.f;
    float o[8][4];
#pragma unroll
    for (int n = 0; n < 8; n++)
#pragma unroll
        for (int e = 0; e < 4; e++) o[n][e] = 0.f;

    uint32_t qf[4][4];
    const int frow  = (lane & 7) + ((lane >> 4) << 3);
    const int fcolb = ((lane >> 3) & 1) << 4;

    for (int it = 0; it < SEQ / 64; it++) {
        if (it + 1 < SEQ / 64) {
            ATT_LOAD((it + 1) & 1, (it + 1) * 64);
            cp_wait1();
        } else {
            cp_wait0();
        }
        __syncthreads();

        if (it == 0) {
            const int arow  = warp * 16 + (lane & 15);
            const int acolb = (lane >> 4) << 4;
#pragma unroll
            for (int kc = 0; kc < 4; kc++)
                ldmx4(qf[kc], sQ + arow * ASTR + kc * 32 + acolb);
        }

        const uint32_t kB = sKV + (it & 1) * 2 * ATILE;
        const uint32_t vB = kB + ATILE;

        /* ---- S = Q K^T ---- */
        float s[8][4];
#pragma unroll
        for (int n = 0; n < 8; n++)
#pragma unroll
            for (int e = 0; e < 4; e++) s[n][e] = 0.f;

#pragma unroll
        for (int kc = 0; kc < 4; kc++)
#pragma unroll
            for (int nb = 0; nb < 4; nb++) {
                uint32_t bhf[4];
                ldmx4(bhf, kB + (nb * 16 + frow) * ASTR + kc * 32 + fcolb);
#pragma unroll
                for (int o2 = 0; o2 < 2; o2++)
                    mma_fp16(s[nb * 2 + o2], qf[kc], bhf[o2 * 2], bhf[o2 * 2 + 1]);
            }

        /* ---- online softmax (rows r and r+8) ---- */
        float mx0 = -1e30f, mx1 = -1e30f;
#pragma unroll
        for (int n = 0; n < 8; n++) {
            mx0 = fmaxf(mx0, fmaxf(s[n][0], s[n][1]));
            mx1 = fmaxf(mx1, fmaxf(s[n][2], s[n][3]));
        }
        mx0 = fmaxf(mx0, __shfl_xor_sync(0xffffffffu, mx0, 1));
        mx0 = fmaxf(mx0, __shfl_xor_sync(0xffffffffu, mx0, 2));
        mx1 = fmaxf(mx1, __shfl_xor_sync(0xffffffffu, mx1, 1));
        mx1 = fmaxf(mx1, __shfl_xor_sync(0xffffffffu, mx1, 2));

        const float mn0 = fmaxf(m0, mx0 * SCALE);
        const float mn1 = fmaxf(m1, mx1 * SCALE);
        const float c0 = __expf(m0 - mn0);
        const float c1 = __expf(m1 - mn1);

        float rs0 = 0.f, rs1 = 0.f;
#pragma unroll
        for (int n = 0; n < 8; n++) {
            s[n][0] = __expf(fmaf(s[n][0], SCALE, -mn0)); rs0 += s[n][0];
            s[n][1] = __expf(fmaf(s[n][1], SCALE, -mn0)); rs0 += s[n][1];
            s[n][2] = __expf(fmaf(s[n][2], SCALE, -mn1)); rs1 += s[n][2];
            s[n][3] = __expf(fmaf(s[n][3], SCALE, -mn1)); rs1 += s[n][3];
        }
        rs0 += __shfl_xor_sync(0xffffffffu, rs0, 1);
        rs0 += __shfl_xor_sync(0xffffffffu, rs0, 2);
        rs1 += __shfl_xor_sync(0xffffffffu, rs1, 1);
        rs1 += __shfl_xor_sync(0xffffffffu, rs1, 2);

        l0 = l0 * c0 + rs0;  l1 = l1 * c1 + rs1;
        m0 = mn0;            m1 = mn1;

#pragma unroll
        for (int n = 0; n < 8; n++) {
            o[n][0] *= c0; o[n][1] *= c0;
            o[n][2] *= c1; o[n][3] *= c1;
        }

        /* ---- O += P V (P repacked in regs as fp16 A-frags) ---- */
#pragma unroll
        for (int kc = 0; kc < 4; kc++) {
            uint32_t af[4];
#pragma unroll
            for (int q2 = 0; q2 < 2; q2++) {
                const int n = 2 * kc + q2;
#pragma unroll
                for (int rh = 0; rh < 2; rh++) {
                    __half2 H = __float22half2_rn(
                        make_float2(s[n][rh * 2 + 0], s[n][rh * 2 + 1]));
                    af[q2 * 2 + rh] = *(uint32_t*)&H;
                }
            }
#pragma unroll
            for (int nb = 0; nb < 4; nb++) {
                uint32_t vf[4];
                ldmx4(vf, vB + (nb * 16 + frow) * ASTR + kc * 32 + fcolb);
#pragma unroll
                for (int o2 = 0; o2 < 2; o2++)
                    mma_fp16(o[nb * 2 + o2], af, vf[o2 * 2], vf[o2 * 2 + 1]);
            }
        }

        __syncthreads();
    }

    /* ---- epilogue: normalize, write fp32 ctx [b, i, h*64+d] ---- */
    const float inv0 = 1.f / l0;
    const float inv1 = 1.f / l1;
    const int r1 = i0 + warp * 16 + (lane >> 2);
    const int h  = bh & 15;
#pragma unroll
    for (int n = 0; n < 8; n++) {
        const int col = h * 64 + n * 8 + (lane & 3) * 2;
        float2 v0 = make_float2(o[n][0] * inv0, o[n][1] * inv0);
        float2 v1 = make_float2(o[n][2] * inv1, o[n][3] * inv1);
        *(float2*)&O[((size_t)(b * SEQ + r1)) * HIDDEN + col]     = v0;
        *(float2*)&O[((size_t)(b * SEQ + r1 + 8)) * HIDDEN + col] = v1;
    }
#undef ATT_LOAD
}

/* ---------------- launch ------------------------------------------------- */
extern "C" void kernel_launch(void* const* d_in, const int* in_sizes, int n_in,
                              void* d_out, int out_size)
{
    (void)in_sizes; (void)n_in; (void)out_size;

    const float* query = (const float*)d_in[0];
    const float* value = (const float*)d_in[1];
    const float* Wq    = (const float*)d_in[2];
    const float* bq    = (const float*)d_in[3];
    const float* Wk    = (const float*)d_in[4];
    const float* bk    = (const float*)d_in[5];
    const float* Wv    = (const float*)d_in[6];
    const float* bv    = (const float*)d_in[7];
    const float* Wo    = (const float*)d_in[8];
    const float* bo    = (const float*)d_in[9];
    float* out = (float*)d_out;

    float *q, *k, *v, *ctx;
    cudaGetSymbolAddress((void**)&q,   g_q);
    cudaGetSymbolAddress((void**)&k,   g_k);
    cudaGetSymbolAddress((void**)&v,   g_v);
    cudaGetSymbolAddress((void**)&ctx, g_ctx);

    __half *qryh, *valh, *ctxh, *wh, *qhp, *khp, *vthp;
    cudaGetSymbolAddress((void**)&qryh, g_qryh);
    cudaGetSymbolAddress((void**)&valh, g_valh);
    cudaGetSymbolAddress((void**)&ctxh, g_ctxh);
    cudaGetSymbolAddress((void**)&wh,   g_wh);
    cudaGetSymbolAddress((void**)&qhp,  g_qh);
    cudaGetSymbolAddress((void**)&khp,  g_kh);
    cudaGetSymbolAddress((void**)&vthp, g_vth);

    cudaFuncSetAttribute(attn_fp16_kernel,
                         cudaFuncAttributeMaxDynamicSharedMemorySize, ASMEM);

    const int nX4 = MTOT * HIDDEN / 4;
    const int nW4 = HIDDEN * HIDDEN / 4;

    cvt4_kernel<<<nX4 / 256, 256>>>((const float4*)query, (uint2*)qryh, nX4);
    cvt4_kernel<<<nX4 / 256, 256>>>((const float4*)value, (uint2*)valh, nX4);
    cvt4_kernel<<<nW4 / 256, 256>>>((const float4*)Wq, (uint2*)(wh + 0 * HIDDEN * HIDDEN), nW4);
    cvt4_kernel<<<nW4 / 256, 256>>>((const float4*)Wk, (uint2*)(wh + 1 * HIDDEN * HIDDEN), nW4);
    cvt4_kernel<<<nW4 / 256, 256>>>((const float4*)Wv, (uint2*)(wh + 2 * HIDDEN * HIDDEN), nW4);
    cvt4_kernel<<<nW4 / 256, 256>>>((const float4*)Wo, (uint2*)(wh + 3 * HIDDEN * HIDDEN), nW4);

    dim3 gg(HIDDEN / 128, MTOT / 128);
    gemm_fp16_kernel<<<gg, 256>>>(qryh, wh + 0 * HIDDEN * HIDDEN, bq, q);
    gemm_fp16_kernel<<<gg, 256>>>(valh, wh + 1 * HIDDEN * HIDDEN, bk, k);
    gemm_fp16_kernel<<<gg, 256>>>(valh, wh + 2 * HIDDEN * HIDDEN, bv, v);

    const int nQK = MTOT * HIDDEN;
    qk_rope_cvt_kernel<<<nQK / 256, 256>>>(q, qhp);
    qk_rope_cvt_kernel<<<nQK / 256, 256>>>(k, khp);
    v_cvt_t_kernel<<<dim3(SEQ / 64, NB * HEADS), 256>>>(v, vthp);

    attn_fp16_kernel<<<dim3(SEQ / 128, NB * HEADS), 256, ASMEM>>>(qhp, khp, vthp, ctx);

    cvt4_kernel<<<nX4 / 256, 256>>>((const float4*)ctx, (uint2*)ctxh, nX4);
    gemm_fp16_kernel<<<gg, 256>>>(ctxh, wh + 3 * HIDDEN * HIDDEN, bo, out);
}

// round 9
// speedup vs baseline: 7.5830x; 1.0862x over previous
#include <cuda_runtime.h>
#include <cuda_fp16.h>
#include <math.h>
#include <stdint.h>

#define HIDDEN 1024
#define HEADS  16
#define KD     64
#define NB     4
#define SEQ    2048
#define MTOT   (NB * SEQ)          /* 8192 rows */
#define SCALE  0.125f              /* 1/sqrt(64) */

/* ---------------- scratch (device globals: no allocs allowed) ------------- */
__device__ __half g_qryh[MTOT * HIDDEN];   /* query fp16 (GEMM A operand) */
__device__ __half g_valh[MTOT * HIDDEN];   /* value fp16 (GEMM A operand) */
__device__ __half g_ctxh[MTOT * HIDDEN];   /* attention output fp16 */
__device__ __half g_wh[4 * HIDDEN * HIDDEN];

/* attention operands: [b,h,s,d] (q,k) and [b,h,d,s] (v transposed) */
__device__ __half g_qh[MTOT * HIDDEN];
__device__ __half g_kh[MTOT * HIDDEN];
__device__ __half g_vth[MTOT * HIDDEN];

/* ======================= PTX helpers (sm_80-portable) ===================== */
__device__ __forceinline__ uint32_t smem_u32(const void* p) {
    uint32_t a;
    asm("{ .reg .u64 t; cvta.to.shared.u64 t, %1; cvt.u32.u64 %0, t; }"
        : "=r"(a) : "l"(p));
    return a;
}
__device__ __forceinline__ void cp16(uint32_t dst, const void* src) {
    asm volatile("cp.async.cg.shared.global [%0], [%1], 16;"
                 :: "r"(dst), "l"(src));
}
__device__ __forceinline__ void cp_commit() {
    asm volatile("cp.async.commit_group;" ::: "memory");
}
__device__ __forceinline__ void cp_wait0() {
    asm volatile("cp.async.wait_group 0;" ::: "memory");
}
__device__ __forceinline__ void cp_wait1() {
    asm volatile("cp.async.wait_group 1;" ::: "memory");
}
__device__ __forceinline__ void ldmx4(uint32_t* r, uint32_t a) {
    asm volatile("ldmatrix.sync.aligned.m8n8.x4.shared.b16 {%0,%1,%2,%3}, [%4];"
                 : "=r"(r[0]), "=r"(r[1]), "=r"(r[2]), "=r"(r[3]) : "r"(a));
}
__device__ __forceinline__ void mma_fp16(float* c, const uint32_t* a,
                                         uint32_t b0, uint32_t b1) {
    asm volatile(
        "mma.sync.aligned.m16n8k16.row.col.f32.f16.f16.f32 "
        "{%0,%1,%2,%3}, {%4,%5,%6,%7}, {%8,%9}, {%0,%1,%2,%3};"
        : "+f"(c[0]), "+f"(c[1]), "+f"(c[2]), "+f"(c[3])
        : "r"(a[0]), "r"(a[1]), "r"(a[2]), "r"(a[3]), "r"(b0), "r"(b1));
}

/* ======================= cvt fp32 -> fp16 ================================= */
__global__ void cvt4_kernel(const float4* __restrict__ x,
                            uint2* __restrict__ out, int n4)
{
    int i = blockIdx.x * blockDim.x + threadIdx.x;
    if (i >= n4) return;
    float4 v = x[i];
    __half2 h0 = __float22half2_rn(make_float2(v.x, v.y));
    __half2 h1 = __float22half2_rn(make_float2(v.z, v.w));
    uint2 o;
    o.x = *(uint32_t*)&h0;
    o.y = *(uint32_t*)&h1;
    out[i] = o;
}

/* ======================= shared GEMM mainloop ============================= *
 * CTA 128x128, 8 warps (2m x 4n), warp tile 64x32, K-chunk 32 (= 64 B rows),
 * 2-stage cp.async, 40 KB static smem. Mainloop emitted via macro so the
 * three epilogue variants share identical (R8-validated) code.
 */
#define GST   80                  /* row stride: 64 B data + 16 B pad */
#define GTILE (128 * GST)         /* 10240 B per tile */

#define GEMM_MAINLOOP()                                                        \
    const int tid  = threadIdx.x;                                              \
    const int lane = tid & 31;                                                 \
    const int warp = tid >> 5;                                                 \
    const int wm   = warp >> 2;                                                \
    const int wn   = warp & 3;                                                 \
    const int bm   = blockIdx.y * 128;                                         \
    const int bn   = blockIdx.x * 128;                                         \
    const uint32_t sb = smem_u32(sm);                                          \
    const __half* srcA = A + (size_t)bm * HIDDEN;                              \
    const __half* srcB = B + (size_t)bn * HIDDEN;                              \
    const int lrow = tid >> 1;                                                 \
    const int lhalf = tid & 1;                                                 \
    float acc[4][4][4];                                                        \
    _Pragma("unroll")                                                          \
    for (int mi = 0; mi < 4; mi++)                                             \
        _Pragma("unroll")                                                      \
        for (int ni = 0; ni < 4; ni++)                                         \
            _Pragma("unroll")                                                  \
            for (int e = 0; e < 4; e++) acc[mi][ni][e] = 0.f;                  \
    G_LOAD(0, 0);                                                              \
    const int arow  = wm * 64 + (lane & 15);                                   \
    const int acolb = (lane >> 4) << 4;                                        \
    const int brow  = wn * 32 + (lane & 7) + ((lane >> 4) << 3);               \
    const int bcolb = ((lane >> 3) & 1) << 4;                                  \
    for (int ck = 0; ck < HIDDEN / 32; ck++) {                                 \
        if (ck < HIDDEN / 32 - 1) {                                            \
            G_LOAD((ck + 1) & 1, (ck + 1) * 32);                               \
            cp_wait1();                                                        \
        } else {                                                               \
            cp_wait0();                                                        \
        }                                                                      \
        __syncthreads();                                                       \
        const uint32_t aB = sb + (ck & 1) * 2 * GTILE;                         \
        const uint32_t bB = aB + GTILE;                                        \
        uint32_t af[2][4][4], bf[2][2][4];                                     \
        _Pragma("unroll")                                                      \
        for (int kc = 0; kc < 2; kc++) {                                       \
            _Pragma("unroll")                                                  \
            for (int mi = 0; mi < 4; mi++)                                     \
                ldmx4(af[kc][mi], aB + (arow + mi * 16) * GST + kc * 32 + acolb); \
            _Pragma("unroll")                                                  \
            for (int nb = 0; nb < 2; nb++)                                     \
                ldmx4(bf[kc][nb], bB + (brow + nb * 16) * GST + kc * 32 + bcolb); \
        }                                                                      \
        _Pragma("unroll")                                                      \
        for (int kc = 0; kc < 2; kc++)                                         \
            _Pragma("unroll")                                                  \
            for (int mi = 0; mi < 4; mi++)                                     \
                _Pragma("unroll")                                              \
                for (int ni = 0; ni < 4; ni++) {                               \
                    const int nb = ni >> 1, o = (ni & 1) * 2;                  \
                    mma_fp16(acc[mi][ni], af[kc][mi], bf[kc][nb][o], bf[kc][nb][o + 1]); \
                }                                                              \
        __syncthreads();                                                       \
    }                                                                          \
    /* bias add (pre-RoPE, matching reference) */                              \
    _Pragma("unroll")                                                          \
    for (int ni = 0; ni < 4; ni++) {                                           \
        const int col = bn + wn * 32 + ni * 8 + (lane & 3) * 2;                \
        const float b0 = bias[col], b1 = bias[col + 1];                        \
        _Pragma("unroll")                                                      \
        for (int mi = 0; mi < 4; mi++) {                                       \
            acc[mi][ni][0] += b0; acc[mi][ni][1] += b1;                        \
            acc[mi][ni][2] += b0; acc[mi][ni][3] += b1;                        \
        }                                                                      \
    }

#define G_LOAD(s, k0)                                                          \
    do {                                                                       \
        uint32_t dA = sb + (s) * 2 * GTILE + lrow * GST + lhalf * 32;          \
        uint32_t dB = dA + GTILE;                                              \
        const __half* pa = srcA + (size_t)lrow * HIDDEN + (k0) + lhalf * 16;   \
        const __half* pb = srcB + (size_t)lrow * HIDDEN + (k0) + lhalf * 16;   \
        cp16(dA, pa);      cp16(dA + 16, pa + 8);                              \
        cp16(dB, pb);      cp16(dB + 16, pb + 8);                              \
        cp_commit();                                                           \
    } while (0)

/* ---- projection GEMM + RoPE, fp16 out [b,h,s,d] (for Q and K) ------------ */
__global__ __launch_bounds__(256)
void gemm_qk_rope_kernel(const __half* __restrict__ A,
                         const __half* __restrict__ B,
                         const float* __restrict__ bias,
                         __half* __restrict__ Yh)
{
    __shared__ __align__(16) char sm[2 * 2 * GTILE];
    GEMM_MAINLOOP();

    /* RoPE: this warp covers cols [bn+wn*32, +32) = one half of one head.
     * If it's the low half (d<32), partner d^16 is fragment ni^2, same thread. */
    if (((bn + wn * 32) & 63) == 0) {
        float thet[2][2];
#pragma unroll
        for (int nl = 0; nl < 2; nl++)
#pragma unroll
            for (int eo = 0; eo < 2; eo++) {
                const int t = nl * 8 + (lane & 3) * 2 + eo;
                thet[nl][eo] = powf(10000.f, -(float)t * (1.f / 16.f));
            }
#pragma unroll
        for (int mi = 0; mi < 4; mi++)
#pragma unroll
            for (int nl = 0; nl < 2; nl++)
#pragma unroll
                for (int e = 0; e < 4; e++) {
                    const int row = bm + wm * 64 + mi * 16 + (lane >> 2) + (e >> 1) * 8;
                    const int s = row & (SEQ - 1);
                    float sn, cs;
                    sincosf((float)s * thet[nl][e & 1], &sn, &cs);
                    const float x0 = acc[mi][nl][e];
                    const float x1 = acc[mi][nl + 2][e];
                    acc[mi][nl][e]     = x0 * cs - x1 * sn;
                    acc[mi][nl + 2][e] = x1 * cs + x0 * sn;
                }
    }

    /* store fp16 [b,h,s,d] */
#pragma unroll
    for (int ni = 0; ni < 4; ni++) {
        const int col = bn + wn * 32 + ni * 8 + (lane & 3) * 2;
        const int h = col >> 6, d = col & 63;
#pragma unroll
        for (int mi = 0; mi < 4; mi++) {
            const int row0 = bm + wm * 64 + mi * 16 + (lane >> 2);
#pragma unroll
            for (int rh = 0; rh < 2; rh++) {
                const int row = row0 + rh * 8;
                const int b = row >> 11, s = row & (SEQ - 1);
                const size_t idx = (((size_t)(b * HEADS + h)) * SEQ + s) * 64 + d;
                *(__half2*)&Yh[idx] = __float22half2_rn(
                    make_float2(acc[mi][ni][rh * 2], acc[mi][ni][rh * 2 + 1]));
            }
        }
    }
}

/* ---- projection GEMM, fp16 out transposed [b,h,d,s] (for V) -------------- */
__global__ __launch_bounds__(256)
void gemm_v_kernel(const __half* __restrict__ A,
                   const __half* __restrict__ B,
                   const float* __restrict__ bias,
                   __half* __restrict__ Yh)
{
    __shared__ __align__(16) char sm[2 * 2 * GTILE];
    GEMM_MAINLOOP();

#pragma unroll
    for (int ni = 0; ni < 4; ni++) {
        const int col = bn + wn * 32 + ni * 8 + (lane & 3) * 2;
        const int h = col >> 6, d = col & 63;
#pragma unroll
        for (int mi = 0; mi < 4; mi++) {
            const int row0 = bm + wm * 64 + mi * 16 + (lane >> 2);
#pragma unroll
            for (int rh = 0; rh < 2; rh++) {
                const int row = row0 + rh * 8;
                const int b = row >> 11, s = row & (SEQ - 1);
                const size_t base = (((size_t)(b * HEADS + h)) * 64 + d) * SEQ + s;
                Yh[base]       = __float2half_rn(acc[mi][ni][rh * 2]);
                Yh[base + SEQ] = __float2half_rn(acc[mi][ni][rh * 2 + 1]);
            }
        }
    }
}

/* ---- output GEMM: fp16 A, fp32 out (final projection) -------------------- */
__global__ __launch_bounds__(256)
void gemm_out_kernel(const __half* __restrict__ A,
                     const __half* __restrict__ B,
                     const float* __restrict__ bias,
                     float* __restrict__ Y)
{
    __shared__ __align__(16) char sm[2 * 2 * GTILE];
    GEMM_MAINLOOP();

#pragma unroll
    for (int ni = 0; ni < 4; ni++) {
        const int col = bn + wn * 32 + ni * 8 + (lane & 3) * 2;
#pragma unroll
        for (int mi = 0; mi < 4; mi++) {
            const int row = bm + wm * 64 + mi * 16 + (lane >> 2);
            *(float2*)&Y[(size_t)row * HIDDEN + col] =
                make_float2(acc[mi][ni][0], acc[mi][ni][1]);
            *(float2*)&Y[(size_t)(row + 8) * HIDDEN + col] =
                make_float2(acc[mi][ni][2], acc[mi][ni][3]);
        }
    }
}

/* ======================= mma.sync flash attention (fp16) ================== *
 * Grid (SEQ/128, NB*HEADS), 256 thr = 8 warps; warp owns 16 q-rows.
 * Bc = 64 per iter, double-buffered cp.async. Writes fp16 ctx directly.
 */
#define ASTR   144
#define ATILE  (64 * ASTR)              /* 9216 B */
#define AQ     (128 * ASTR)             /* 18432 B */
#define ASMEM  (AQ + 2 * 2 * ATILE)     /* 55296 B */

__global__ __launch_bounds__(256)
void attn_fp16_kernel(const __half* __restrict__ qh,
                      const __half* __restrict__ kh,
                      const __half* __restrict__ vth,
                      __half* __restrict__ O)
{
    extern __shared__ __align__(16) char sm[];
    const uint32_t sb = smem_u32(sm);
    const int tid  = threadIdx.x;
    const int lane = tid & 31;
    const int warp = tid >> 5;
    const int bh   = blockIdx.y;
    const int b    = bh >> 4;
    const int i0   = blockIdx.x * 128;

    const uint32_t sQ  = sb;
    const uint32_t sKV = sb + AQ;

    /* ---- prologue: Q tile (128 rows x 128 B), folds into group 0 ---- */
    {
        const int r = tid >> 3, ch = tid & 7;
        const size_t qbase = ((size_t)bh * SEQ + i0) * 64;
#pragma unroll
        for (int k4 = 0; k4 < 4; k4++) {
            const int row = r + k4 * 32;
            cp16(sQ + row * ASTR + ch * 16, qh + qbase + (size_t)row * 64 + ch * 8);
        }
    }

#define ATT_LOAD(buf, j0)                                                       \
    do {                                                                        \
        const int r_ = tid >> 3, ch_ = tid & 7;                                 \
        const uint32_t kb_ = sKV + (buf) * 2 * ATILE;                           \
        _Pragma("unroll")                                                       \
        for (int hf = 0; hf < 2; hf++) {                                        \
            const int row = r_ + hf * 32;                                       \
            const size_t ks = ((size_t)bh * SEQ + (j0) + row) * 64 + ch_ * 8;   \
            const size_t vs = ((size_t)bh * 64 + row) * SEQ + (j0) + ch_ * 8;   \
            cp16(kb_ + row * ASTR + ch_ * 16,         kh + ks);                 \
            cp16(kb_ + ATILE + row * ASTR + ch_ * 16, vth + vs);                \
        }                                                                       \
        cp_commit();                                                            \
    } while (0)

    ATT_LOAD(0, 0);

    float m0 = -1e30f, m1 = -1e30f, l0 = 0.f, l1 = 0.f;
    float o[8][4];
#pragma unroll
    for (int n = 0; n < 8; n++)
#pragma unroll
        for (int e = 0; e < 4; e++) o[n][e] = 0.f;

    uint32_t qf[4][4];
    const int frow  = (lane & 7) + ((lane >> 4) << 3);
    const int fcolb = ((lane >> 3) & 1) << 4;

    for (int it = 0; it < SEQ / 64; it++) {
        if (it + 1 < SEQ / 64) {
            ATT_LOAD((it + 1) & 1, (it + 1) * 64);
            cp_wait1();
        } else {
            cp_wait0();
        }
        __syncthreads();

        if (it == 0) {
            const int arow  = warp * 16 + (lane & 15);
            const int acolb = (lane >> 4) << 4;
#pragma unroll
            for (int kc = 0; kc < 4; kc++)
                ldmx4(qf[kc], sQ + arow * ASTR + kc * 32 + acolb);
        }

        const uint32_t kB = sKV + (it & 1) * 2 * ATILE;
        const uint32_t vB = kB + ATILE;

        /* ---- S = Q K^T ---- */
        float s[8][4];
#pragma unroll
        for (int n = 0; n < 8; n++)
#pragma unroll
            for (int e = 0; e < 4; e++) s[n][e] = 0.f;

#pragma unroll
        for (int kc = 0; kc < 4; kc++)
#pragma unroll
            for (int nb = 0; nb < 4; nb++) {
                uint32_t bhf[4];
                ldmx4(bhf, kB + (nb * 16 + frow) * ASTR + kc * 32 + fcolb);
#pragma unroll
                for (int o2 = 0; o2 < 2; o2++)
                    mma_fp16(s[nb * 2 + o2], qf[kc], bhf[o2 * 2], bhf[o2 * 2 + 1]);
            }

        /* ---- online softmax (rows r and r+8) ---- */
        float mx0 = -1e30f, mx1 = -1e30f;
#pragma unroll
        for (int n = 0; n < 8; n++) {
            mx0 = fmaxf(mx0, fmaxf(s[n][0], s[n][1]));
            mx1 = fmaxf(mx1, fmaxf(s[n][2], s[n][3]));
        }
        mx0 = fmaxf(mx0, __shfl_xor_sync(0xffffffffu, mx0, 1));
        mx0 = fmaxf(mx0, __shfl_xor_sync(0xffffffffu, mx0, 2));
        mx1 = fmaxf(mx1, __shfl_xor_sync(0xffffffffu, mx1, 1));
        mx1 = fmaxf(mx1, __shfl_xor_sync(0xffffffffu, mx1, 2));

        const float mn0 = fmaxf(m0, mx0 * SCALE);
        const float mn1 = fmaxf(m1, mx1 * SCALE);
        const float c0 = __expf(m0 - mn0);
        const float c1 = __expf(m1 - mn1);

        float rs0 = 0.f, rs1 = 0.f;
#pragma unroll
        for (int n = 0; n < 8; n++) {
            s[n][0] = __expf(fmaf(s[n][0], SCALE, -mn0)); rs0 += s[n][0];
            s[n][1] = __expf(fmaf(s[n][1], SCALE, -mn0)); rs0 += s[n][1];
            s[n][2] = __expf(fmaf(s[n][2], SCALE, -mn1)); rs1 += s[n][2];
            s[n][3] = __expf(fmaf(s[n][3], SCALE, -mn1)); rs1 += s[n][3];
        }
        rs0 += __shfl_xor_sync(0xffffffffu, rs0, 1);
        rs0 += __shfl_xor_sync(0xffffffffu, rs0, 2);
        rs1 += __shfl_xor_sync(0xffffffffu, rs1, 1);
        rs1 += __shfl_xor_sync(0xffffffffu, rs1, 2);

        l0 = l0 * c0 + rs0;  l1 = l1 * c1 + rs1;
        m0 = mn0;            m1 = mn1;

#pragma unroll
        for (int n = 0; n < 8; n++) {
            o[n][0] *= c0; o[n][1] *= c0;
            o[n][2] *= c1; o[n][3] *= c1;
        }

        /* ---- O += P V (P repacked in regs as fp16 A-frags) ---- */
#pragma unroll
        for (int kc = 0; kc < 4; kc++) {
            uint32_t af[4];
#pragma unroll
            for (int q2 = 0; q2 < 2; q2++) {
                const int n = 2 * kc + q2;
#pragma unroll
                for (int rh = 0; rh < 2; rh++) {
                    __half2 H = __float22half2_rn(
                        make_float2(s[n][rh * 2 + 0], s[n][rh * 2 + 1]));
                    af[q2 * 2 + rh] = *(uint32_t*)&H;
                }
            }
#pragma unroll
            for (int nb = 0; nb < 4; nb++) {
                uint32_t vf[4];
                ldmx4(vf, vB + (nb * 16 + frow) * ASTR + kc * 32 + fcolb);
#pragma unroll
                for (int o2 = 0; o2 < 2; o2++)
                    mma_fp16(o[nb * 2 + o2], af, vf[o2 * 2], vf[o2 * 2 + 1]);
            }
        }

        __syncthreads();
    }

    /* ---- epilogue: normalize, write fp16 ctx [b, i, h*64+d] ---- */
    const float inv0 = 1.f / l0;
    const float inv1 = 1.f / l1;
    const int r1 = i0 + warp * 16 + (lane >> 2);
    const int h  = bh & 15;
#pragma unroll
    for (int n = 0; n < 8; n++) {
        const int col = h * 64 + n * 8 + (lane & 3) * 2;
        *(__half2*)&O[((size_t)(b * SEQ + r1)) * HIDDEN + col] =
            __float22half2_rn(make_float2(o[n][0] * inv0, o[n][1] * inv0));
        *(__half2*)&O[((size_t)(b * SEQ + r1 + 8)) * HIDDEN + col] =
            __float22half2_rn(make_float2(o[n][2] * inv1, o[n][3] * inv1));
    }
#undef ATT_LOAD
}

/* ---------------- launch ------------------------------------------------- */
extern "C" void kernel_launch(void* const* d_in, const int* in_sizes, int n_in,
                              void* d_out, int out_size)
{
    (void)in_sizes; (void)n_in; (void)out_size;

    const float* query = (const float*)d_in[0];
    const float* value = (const float*)d_in[1];
    const float* Wq    = (const float*)d_in[2];
    const float* bq    = (const float*)d_in[3];
    const float* Wk    = (const float*)d_in[4];
    const float* bk    = (const float*)d_in[5];
    const float* Wv    = (const float*)d_in[6];
    const float* bv    = (const float*)d_in[7];
    const float* Wo    = (const float*)d_in[8];
    const float* bo    = (const float*)d_in[9];
    float* out = (float*)d_out;

    __half *qryh, *valh, *ctxh, *wh, *qhp, *khp, *vthp;
    cudaGetSymbolAddress((void**)&qryh, g_qryh);
    cudaGetSymbolAddress((void**)&valh, g_valh);
    cudaGetSymbolAddress((void**)&ctxh, g_ctxh);
    cudaGetSymbolAddress((void**)&wh,   g_wh);
    cudaGetSymbolAddress((void**)&qhp,  g_qh);
    cudaGetSymbolAddress((void**)&khp,  g_kh);
    cudaGetSymbolAddress((void**)&vthp, g_vth);

    cudaFuncSetAttribute(attn_fp16_kernel,
                         cudaFuncAttributeMaxDynamicSharedMemorySize, ASMEM);

    const int nX4 = MTOT * HIDDEN / 4;
    const int nW4 = HIDDEN * HIDDEN / 4;

    cvt4_kernel<<<nX4 / 256, 256>>>((const float4*)query, (uint2*)qryh, nX4);
    cvt4_kernel<<<nX4 / 256, 256>>>((const float4*)value, (uint2*)valh, nX4);
    cvt4_kernel<<<nW4 / 256, 256>>>((const float4*)Wq, (uint2*)(wh + 0 * HIDDEN * HIDDEN), nW4);
    cvt4_kernel<<<nW4 / 256, 256>>>((const float4*)Wk, (uint2*)(wh + 1 * HIDDEN * HIDDEN), nW4);
    cvt4_kernel<<<nW4 / 256, 256>>>((const float4*)Wv, (uint2*)(wh + 2 * HIDDEN * HIDDEN), nW4);
    cvt4_kernel<<<nW4 / 256, 256>>>((const float4*)Wo, (uint2*)(wh + 3 * HIDDEN * HIDDEN), nW4);

    dim3 gg(HIDDEN / 128, MTOT / 128);
    gemm_qk_rope_kernel<<<gg, 256>>>(qryh, wh + 0 * HIDDEN * HIDDEN, bq, qhp);
    gemm_qk_rope_kernel<<<gg, 256>>>(valh, wh + 1 * HIDDEN * HIDDEN, bk, khp);
    gemm_v_kernel<<<gg, 256>>>(valh, wh + 2 * HIDDEN * HIDDEN, bv, vthp);

    attn_fp16_kernel<<<dim3(SEQ / 128, NB * HEADS), 256, ASMEM>>>(qhp, khp, vthp, ctxh);

    gemm_out_kernel<<<gg, 256>>>(ctxh, wh + 3 * HIDDEN * HIDDEN, bo, out);
}